// round 2
// baseline (speedup 1.0000x reference)
#include <cuda_runtime.h>
#include <cstdint>
#include <cfloat>

#define N_PTS 8192
#define KNN   16
#define CIN   256
#define COUT  256
#define NK    (N_PTS*KNN)       // 131072
#define HDIM  64
#define SLOPE 0.01f
#define EPS   1e-5f
#define TILE  1024
#define QPB   8

// ---------------- device scratch (static, allocation-free) ----------------
__device__ int   g_idx[NK];
__device__ float g_q [N_PTS*COUT];
__device__ float g_kf[N_PTS*COUT];
__device__ float g_vf[N_PTS*COUT];
__device__ float g_h [NK*HDIM];        // 32 MB
__device__ float g_pe[NK*COUT];        // 128 MB
__device__ float g_w1[NK*COUT];        // 128 MB
__device__ float g_w2[NK*COUT];        // 128 MB
// BN stats: pe(64ch), w1(256ch), w2(256ch)
__device__ float g_psum[HDIM], g_pssq[HDIM], g_pscale[HDIM], g_pshift[HDIM];
__device__ float g_s1[COUT], g_q1[COUT], g_sc1[COUT], g_sh1[COUT];
__device__ float g_s2[COUT], g_q2[COUT], g_sc2[COUT], g_sh2[COUT];

// ---------------- zero stats ----------------
__global__ void zero_stats_kernel() {
    int t = threadIdx.x;
    if (t < HDIM) { g_psum[t] = 0.f; g_pssq[t] = 0.f; }
    if (t < COUT) { g_s1[t] = 0.f; g_q1[t] = 0.f; g_s2[t] = 0.f; g_q2[t] = 0.f; }
}

// ---------------- kNN ----------------
// d2 must match the reference's fp32 rounding structure:
//   sn = fl(fl(x*x + y*y) + z*z)   (separately rounded products, sequential sum)
//   t  = fma-ascending dot: t = x*xi; t = fma(y,yi,t); t = fma(z,zi,t)
//   d2 = fl(fl(sn+si) - fl(2*t))
// All via _rn intrinsics so ptxas cannot re-contract.
__device__ __forceinline__ float norm3_ref(float x, float y, float z) {
    return __fadd_rn(__fadd_rn(__fmul_rn(x, x), __fmul_rn(y, y)), __fmul_rn(z, z));
}

__global__ void knn_kernel(const float* __restrict__ xyz_i,
                           const float* __restrict__ xyz_last) {
    __shared__ float sx[TILE], sy[TILE], sz[TILE], sn2[TILE];
    __shared__ float ld[QPB][KNN][32];
    __shared__ int   li[QPB][KNN][32];
    const int tid = threadIdx.x;
    const int w = tid >> 5, lane = tid & 31;
    const int q = blockIdx.x * QPB + w;
    const float qx = xyz_last[q*3+0];
    const float qy = xyz_last[q*3+1];
    const float qz = xyz_last[q*3+2];
    const float nq = norm3_ref(qx, qy, qz);
#pragma unroll
    for (int j = 0; j < KNN; j++) { ld[w][j][lane] = FLT_MAX; li[w][j][lane] = 0x7fffffff; }

    for (int t0 = 0; t0 < N_PTS; t0 += TILE) {
        __syncthreads();
        for (int p = tid; p < TILE; p += 256) {
            float x = xyz_i[(t0+p)*3+0];
            float y = xyz_i[(t0+p)*3+1];
            float z = xyz_i[(t0+p)*3+2];
            sx[p] = x; sy[p] = y; sz[p] = z;
            sn2[p] = norm3_ref(x, y, z);
        }
        __syncthreads();
        for (int i = lane; i < TILE; i += 32) {
            float px = sx[i], py = sy[i], pz = sz[i];
            float t = __fmul_rn(qx, px);
            t = __fmaf_rn(qy, py, t);
            t = __fmaf_rn(qz, pz, t);
            float d2 = __fsub_rn(__fadd_rn(nq, sn2[i]), __fmul_rn(2.0f, t));
            if (d2 < ld[w][KNN-1][lane]) {
                int gi = t0 + i;
                int j = KNN - 1;
                while (j > 0 && ld[w][j-1][lane] > d2) {
                    ld[w][j][lane] = ld[w][j-1][lane];
                    li[w][j][lane] = li[w][j-1][lane];
                    j--;
                }
                ld[w][j][lane] = d2;
                li[w][j][lane] = gi;
            }
        }
    }
    // merge 32 sorted per-lane lists -> global top-16
    // tie-break: lower global index wins (lax.top_k is stable)
    int pos = 0;
    for (int r = 0; r < KNN; r++) {
        float v = (pos < KNN) ? ld[w][pos][lane] : FLT_MAX;
        int  gi = (pos < KNN) ? li[w][pos][lane] : 0x7fffffff;
        int  owner = lane;
#pragma unroll
        for (int off = 16; off > 0; off >>= 1) {
            float v2  = __shfl_xor_sync(0xffffffffu, v, off);
            int   g2  = __shfl_xor_sync(0xffffffffu, gi, off);
            int   o2  = __shfl_xor_sync(0xffffffffu, owner, off);
            if (v2 < v || (v2 == v && g2 < gi)) { v = v2; gi = g2; owner = o2; }
        }
        if (lane == 0) g_idx[q*KNN + r] = gi;
        if (lane == owner) pos++;
    }
}

// ---------------- generic fp32 SGEMM: C[M,N] = f(A)[M,K] @ B[K,N] + bias ----------------
// mode 0: f = identity; mode 1: f = lrelu(x*g_pscale[k]+g_pshift[k]);
// mode 2: f = lrelu(x*g_sc1[k]+g_sh1[k])
__global__ void sgemm_kernel(const float* __restrict__ A,
                             const float* __restrict__ B,
                             const float* __restrict__ bias,
                             float* __restrict__ C,
                             int M, int N, int K, int mode) {
    __shared__ float As[8][132];
    __shared__ float Bs[8][128];
    const float* scale = (mode == 1) ? g_pscale : g_sc1;
    const float* shift = (mode == 1) ? g_pshift : g_sh1;
    const int tid = threadIdx.x;
    const int tx = tid & 15, ty = tid >> 4;
    const int m0 = blockIdx.y * 128, n0 = blockIdx.x * 128;
    const int arow = tid >> 1, ac4 = (tid & 1) * 4;
    const int brow = tid >> 5, bc4 = (tid & 31) * 4;
    float acc[8][8];
#pragma unroll
    for (int i = 0; i < 8; i++)
#pragma unroll
        for (int j = 0; j < 8; j++) acc[i][j] = 0.f;

    for (int kt = 0; kt < K; kt += 8) {
        float4 av = *(const float4*)(A + (size_t)(m0 + arow)*K + kt + ac4);
        if (mode != 0) {
            int kb = kt + ac4;
            float x;
            x = av.x*scale[kb+0] + shift[kb+0]; av.x = (x >= 0.f) ? x : SLOPE*x;
            x = av.y*scale[kb+1] + shift[kb+1]; av.y = (x >= 0.f) ? x : SLOPE*x;
            x = av.z*scale[kb+2] + shift[kb+2]; av.z = (x >= 0.f) ? x : SLOPE*x;
            x = av.w*scale[kb+3] + shift[kb+3]; av.w = (x >= 0.f) ? x : SLOPE*x;
        }
        As[ac4+0][arow] = av.x;
        As[ac4+1][arow] = av.y;
        As[ac4+2][arow] = av.z;
        As[ac4+3][arow] = av.w;
        *(float4*)&Bs[brow][bc4] = *(const float4*)(B + (size_t)(kt + brow)*N + n0 + bc4);
        __syncthreads();
#pragma unroll
        for (int kk = 0; kk < 8; kk++) {
            float a[8], b[8];
#pragma unroll
            for (int i = 0; i < 8; i++) a[i] = As[kk][ty + 16*i];
#pragma unroll
            for (int j = 0; j < 8; j++) b[j] = Bs[kk][tx + 16*j];
#pragma unroll
            for (int i = 0; i < 8; i++)
#pragma unroll
                for (int j = 0; j < 8; j++) acc[i][j] = fmaf(a[i], b[j], acc[i][j]);
        }
        __syncthreads();
    }
#pragma unroll
    for (int i = 0; i < 8; i++) {
        int m = m0 + ty + 16*i;
#pragma unroll
        for (int j = 0; j < 8; j++) {
            int nn = n0 + tx + 16*j;
            C[(size_t)m*N + nn] = acc[i][j] + bias[nn];
        }
    }
}

// ---------------- pe stage 1: h[s,c] = pe4(s) . wp1[:,c] + bp1[c] ----------------
__global__ void pe1_kernel(const float* __restrict__ xyz_i,
                           const float* __restrict__ xyz_last,
                           const float* __restrict__ t_i,
                           const float* __restrict__ t_last,
                           const float* __restrict__ wp1,
                           const float* __restrict__ bp1) {
    int gid = blockIdx.x * 256 + threadIdx.x;       // NK*HDIM threads
    int s = gid >> 6, c = gid & 63;
    int n = s >> 4;
    int j = g_idx[s];
    float dt = t_i[0] - t_last[0];
    float px = xyz_i[j*3+0] - xyz_last[n*3+0];
    float py = xyz_i[j*3+1] - xyz_last[n*3+1];
    float pz = xyz_i[j*3+2] - xyz_last[n*3+2];
    float h = bp1[c];
    h = fmaf(px, wp1[c],        h);
    h = fmaf(py, wp1[64 + c],   h);
    h = fmaf(pz, wp1[128 + c],  h);
    h = fmaf(dt, wp1[192 + c],  h);
    g_h[gid] = h;
}

// ---------------- per-channel sum / sumsq (BN stats) ----------------
__global__ void stats_kernel(const float* __restrict__ X, int M, int C, int which) {
    float* gs = (which == 0) ? g_psum : ((which == 1) ? g_s1 : g_s2);
    float* gq = (which == 0) ? g_pssq : ((which == 1) ? g_q1 : g_q2);
    int c = threadIdx.x;                 // blockDim.x == C
    float s = 0.f, q = 0.f;
    for (int r = blockIdx.x; r < M; r += gridDim.x) {
        float x = X[(size_t)r*C + c];
        s += x; q = fmaf(x, x, q);
    }
    atomicAdd(&gs[c], s);
    atomicAdd(&gq[c], q);
}

__global__ void finalize_kernel(const float* __restrict__ gamma,
                                const float* __restrict__ beta,
                                float invM, int which) {
    int c = threadIdx.x;
    const float* gs = (which == 0) ? g_psum : ((which == 1) ? g_s1 : g_s2);
    const float* gq = (which == 0) ? g_pssq : ((which == 1) ? g_q1 : g_q2);
    float* sc = (which == 0) ? g_pscale : ((which == 1) ? g_sc1 : g_sc2);
    float* sh = (which == 0) ? g_pshift : ((which == 1) ? g_sh1 : g_sh2);
    float m = gs[c] * invM;
    float v = gq[c] * invM - m*m;
    float s = gamma[c] * rsqrtf(v + EPS);
    sc[c] = s;
    sh[c] = beta[c] - m*s;
}

// ---------------- w1 = q[n] - kf[idx] + pe ----------------
__global__ void w1_kernel() {
    size_t gid = (size_t)blockIdx.x * 256 + threadIdx.x;   // NK*COUT
    int c = (int)(gid & 255);
    size_t s = gid >> 8;
    int n = (int)(s >> 4);
    int j = g_idx[s];
    g_w1[gid] = g_q[(size_t)n*COUT + c] - g_kf[(size_t)j*COUT + c] + g_pe[gid];
}

// ---------------- final: bn2 + lrelu + softmax(K) + weighted v-sum ----------------
__global__ void final_kernel(float* __restrict__ out) {
    int n = blockIdx.x, c = threadIdx.x;
    __shared__ int sidx[KNN];
    if (c < KNN) sidx[c] = g_idx[n*KNN + c];
    __syncthreads();
    float sc = g_sc2[c], sh = g_sh2[c];
    float z[KNN];
    float m = -FLT_MAX;
#pragma unroll
    for (int k = 0; k < KNN; k++) {
        float x = g_w2[((size_t)n*KNN + k)*COUT + c];
        x = x*sc + sh;
        x = (x >= 0.f) ? x : SLOPE*x;
        z[k] = x;
        m = fmaxf(m, x);
    }
    float den = 0.f, num = 0.f;
#pragma unroll
    for (int k = 0; k < KNN; k++) {
        float e = __expf(z[k] - m);
        float v = g_vf[(size_t)sidx[k]*COUT + c] + g_pe[((size_t)n*KNN + k)*COUT + c];
        den += e;
        num = fmaf(e, v, num);
    }
    out[(size_t)n*COUT + c] = num / den;
}

// ---------------- launch ----------------
extern "C" void kernel_launch(void* const* d_in, const int* in_sizes, int n_in,
                              void* d_out, int out_size) {
    const float* fea_i    = (const float*)d_in[0];
    const float* fea_last = (const float*)d_in[1];
    const float* xyz_i    = (const float*)d_in[2];
    const float* xyz_last = (const float*)d_in[3];
    const float* t_i      = (const float*)d_in[4];
    const float* t_last   = (const float*)d_in[5];
    const float* wp1 = (const float*)d_in[6];
    const float* bp1 = (const float*)d_in[7];
    const float* gp  = (const float*)d_in[8];
    const float* bp  = (const float*)d_in[9];
    const float* wp2 = (const float*)d_in[10];
    const float* bp2 = (const float*)d_in[11];
    const float* wq  = (const float*)d_in[12];
    const float* bq  = (const float*)d_in[13];
    const float* wk  = (const float*)d_in[14];
    const float* bk  = (const float*)d_in[15];
    const float* wv  = (const float*)d_in[16];
    const float* bv  = (const float*)d_in[17];
    const float* gw1 = (const float*)d_in[18];
    const float* bw1 = (const float*)d_in[19];
    const float* ww  = (const float*)d_in[20];
    const float* bw  = (const float*)d_in[21];
    const float* gw2 = (const float*)d_in[22];
    const float* bw2 = (const float*)d_in[23];
    float* out = (float*)d_out;

    void* p;
    cudaGetSymbolAddress(&p, g_q);  float* p_q  = (float*)p;
    cudaGetSymbolAddress(&p, g_kf); float* p_kf = (float*)p;
    cudaGetSymbolAddress(&p, g_vf); float* p_vf = (float*)p;
    cudaGetSymbolAddress(&p, g_h);  float* p_h  = (float*)p;
    cudaGetSymbolAddress(&p, g_pe); float* p_pe = (float*)p;
    cudaGetSymbolAddress(&p, g_w1); float* p_w1 = (float*)p;
    cudaGetSymbolAddress(&p, g_w2); float* p_w2 = (float*)p;

    zero_stats_kernel<<<1, 256>>>();

    // 1) kNN
    knn_kernel<<<N_PTS/QPB, 256>>>(xyz_i, xyz_last);

    // 2) projections (gather/linear commuted: project first, gather later)
    dim3 gProj(COUT/128, N_PTS/128);
    sgemm_kernel<<<gProj, 256>>>(fea_last, wq, bq, p_q,  N_PTS, COUT, CIN, 0);
    sgemm_kernel<<<gProj, 256>>>(fea_i,    wk, bk, p_kf, N_PTS, COUT, CIN, 0);
    sgemm_kernel<<<gProj, 256>>>(fea_i,    wv, bv, p_vf, N_PTS, COUT, CIN, 0);

    // 3) pe: h = pe4@wp1+bp1, BN stats, then pe = lrelu(bn(h)) @ wp2 + bp2
    pe1_kernel<<<(NK*HDIM)/256, 256>>>(xyz_i, xyz_last, t_i, t_last, wp1, bp1);
    stats_kernel<<<512, HDIM>>>(p_h, NK, HDIM, 0);
    finalize_kernel<<<1, HDIM>>>(gp, bp, 1.f/(float)NK, 0);
    dim3 gBig(COUT/128, NK/128);
    sgemm_kernel<<<gBig, 256>>>(p_h, wp2, bp2, p_pe, NK, COUT, HDIM, 1);

    // 4) w1 = q - kf[idx] + pe, BN1 stats
    w1_kernel<<<(NK*COUT)/256, 256>>>();
    stats_kernel<<<512, COUT>>>(p_w1, NK, COUT, 1);
    finalize_kernel<<<1, COUT>>>(gw1, bw1, 1.f/(float)NK, 1);

    // 5) w2 = lrelu(bn1(w1)) @ ww + bw, BN2 stats
    sgemm_kernel<<<gBig, 256>>>(p_w1, ww, bw, p_w2, NK, COUT, CIN, 2);
    stats_kernel<<<512, COUT>>>(p_w2, NK, COUT, 2);
    finalize_kernel<<<1, COUT>>>(gw2, bw2, 1.f/(float)NK, 2);

    // 6) softmax over K + weighted sum of v = vf[idx] + pe
    final_kernel<<<N_PTS, COUT>>>(out);
}

// round 3
// speedup vs baseline: 1.2357x; 1.2357x over previous
#include <cuda_runtime.h>
#include <cstdint>
#include <cfloat>

#define N_PTS 8192
#define KNN   16
#define CIN   256
#define COUT  256
#define NK    (N_PTS*KNN)       // 131072
#define HDIM  64
#define SLOPE 0.01f
#define EPS   1e-5f
#define TILE  1024
#define QPB   8

// ---------------- device scratch (static, allocation-free) ----------------
__device__ int   g_idx[NK];
__device__ float g_q  [N_PTS*COUT];
__device__ float g_kv [N_PTS*512];     // [kf | vf] 16 MB
__device__ float g_wkv[CIN*512];       // [wk | wv]
__device__ float g_bkv[512];
__device__ float g_h  [NK*HDIM];       // 32 MB
__device__ float g_pe [NK*COUT];       // 128 MB
__device__ float g_w1 [NK*COUT];       // 128 MB
__device__ float g_w2 [NK*COUT];       // 128 MB
// BN stats: pe(64ch), w1(256ch), w2(256ch)
__device__ float g_psum[HDIM], g_pssq[HDIM], g_pscale[HDIM], g_pshift[HDIM];
__device__ float g_s1[COUT], g_q1[COUT], g_sc1[COUT], g_sh1[COUT];
__device__ float g_s2[COUT], g_q2[COUT], g_sc2[COUT], g_sh2[COUT];

// ---------------- zero stats ----------------
__global__ void zero_stats_kernel() {
    int t = threadIdx.x;
    if (t < HDIM) { g_psum[t] = 0.f; g_pssq[t] = 0.f; }
    if (t < COUT) { g_s1[t] = 0.f; g_q1[t] = 0.f; g_s2[t] = 0.f; g_q2[t] = 0.f; }
}

// ---------------- weight concat for fused kf/vf projection ----------------
__global__ void concat_kv_kernel(const float* __restrict__ wk, const float* __restrict__ wv,
                                 const float* __restrict__ bk, const float* __restrict__ bv) {
    int i = blockIdx.x * 256 + threadIdx.x;            // CIN*512 threads
    int k = i >> 9, c = i & 511;
    g_wkv[i] = (c < 256) ? wk[k*256 + c] : wv[k*256 + c - 256];
    if (i < 512) g_bkv[i] = (i < 256) ? bk[i] : bv[i - 256];
}

// ---------------- kNN (bit-identical to passing version) ----------------
__device__ __forceinline__ float norm3_ref(float x, float y, float z) {
    return __fadd_rn(__fadd_rn(__fmul_rn(x, x), __fmul_rn(y, y)), __fmul_rn(z, z));
}

__global__ void knn_kernel(const float* __restrict__ xyz_i,
                           const float* __restrict__ xyz_last) {
    __shared__ float sx[TILE], sy[TILE], sz[TILE], sn2[TILE];
    __shared__ float ld[QPB][KNN][32];
    __shared__ int   li[QPB][KNN][32];
    const int tid = threadIdx.x;
    const int w = tid >> 5, lane = tid & 31;
    const int q = blockIdx.x * QPB + w;
    const float qx = xyz_last[q*3+0];
    const float qy = xyz_last[q*3+1];
    const float qz = xyz_last[q*3+2];
    const float nq = norm3_ref(qx, qy, qz);
#pragma unroll
    for (int j = 0; j < KNN; j++) { ld[w][j][lane] = FLT_MAX; li[w][j][lane] = 0x7fffffff; }

    for (int t0 = 0; t0 < N_PTS; t0 += TILE) {
        __syncthreads();
        for (int p = tid; p < TILE; p += 256) {
            float x = xyz_i[(t0+p)*3+0];
            float y = xyz_i[(t0+p)*3+1];
            float z = xyz_i[(t0+p)*3+2];
            sx[p] = x; sy[p] = y; sz[p] = z;
            sn2[p] = norm3_ref(x, y, z);
        }
        __syncthreads();
        for (int i = lane; i < TILE; i += 32) {
            float px = sx[i], py = sy[i], pz = sz[i];
            float t = __fmul_rn(qx, px);
            t = __fmaf_rn(qy, py, t);
            t = __fmaf_rn(qz, pz, t);
            float d2 = __fsub_rn(__fadd_rn(nq, sn2[i]), __fmul_rn(2.0f, t));
            if (d2 < ld[w][KNN-1][lane]) {
                int gi = t0 + i;
                int j = KNN - 1;
                while (j > 0 && ld[w][j-1][lane] > d2) {
                    ld[w][j][lane] = ld[w][j-1][lane];
                    li[w][j][lane] = li[w][j-1][lane];
                    j--;
                }
                ld[w][j][lane] = d2;
                li[w][j][lane] = gi;
            }
        }
    }
    int pos = 0;
    for (int r = 0; r < KNN; r++) {
        float v = (pos < KNN) ? ld[w][pos][lane] : FLT_MAX;
        int  gi = (pos < KNN) ? li[w][pos][lane] : 0x7fffffff;
        int  owner = lane;
#pragma unroll
        for (int off = 16; off > 0; off >>= 1) {
            float v2  = __shfl_xor_sync(0xffffffffu, v, off);
            int   g2  = __shfl_xor_sync(0xffffffffu, gi, off);
            int   o2  = __shfl_xor_sync(0xffffffffu, owner, off);
            if (v2 < v || (v2 == v && g2 < gi)) { v = v2; gi = g2; owner = o2; }
        }
        if (lane == 0) g_idx[q*KNN + r] = gi;
        if (lane == owner) pos++;
    }
}

// ---------------- SGEMM: C[M,N] = f(A)[M,K] @ B[K,N] + bias, fused epilogues ----
// MODE 0: plain (projections)
// MODE 1: f = lrelu(x*pscale+pshift); epilogue writes C(=pe) AND g_w1 = q - kf[idx] + pe,
//         accumulating BN1 stats of w1
// MODE 2: f = lrelu(x*sc1+sh1); epilogue writes C(=w2) and accumulates BN2 stats
template<int MODE>
__global__ __launch_bounds__(256, 2)
void sgemm_kernel(const float* __restrict__ A,
                  const float* __restrict__ B,
                  const float* __restrict__ bias,
                  float* __restrict__ C,
                  int M, int N, int K) {
    __shared__ float As[16][132];
    __shared__ float Bs[16][128];
    const int tid = threadIdx.x;
    const int tx = tid & 15, ty = tid >> 4;
    const int m0 = blockIdx.y * 128, n0 = blockIdx.x * 128;
    const int ar = tid >> 2, ac4 = (tid & 3) * 4;    // A loader: 2 rows (ar, ar+64)
    const int br = tid >> 5, bc4 = (tid & 31) * 4;   // B loader: 2 rows (br, br+8)
    const float* scale = (MODE == 1) ? g_pscale : g_sc1;
    const float* shift = (MODE == 1) ? g_pshift : g_sh1;

    float acc[8][8];
#pragma unroll
    for (int i = 0; i < 8; i++)
#pragma unroll
        for (int j = 0; j < 8; j++) acc[i][j] = 0.f;

    for (int kt = 0; kt < K; kt += 16) {
#pragma unroll
        for (int i = 0; i < 2; i++) {
            int r = ar + i * 64;
            float4 av = *(const float4*)(A + (size_t)(m0 + r)*K + kt + ac4);
            if (MODE != 0) {
                int kb = kt + ac4;
                float x;
                x = fmaf(av.x, scale[kb+0], shift[kb+0]); av.x = (x >= 0.f) ? x : SLOPE*x;
                x = fmaf(av.y, scale[kb+1], shift[kb+1]); av.y = (x >= 0.f) ? x : SLOPE*x;
                x = fmaf(av.z, scale[kb+2], shift[kb+2]); av.z = (x >= 0.f) ? x : SLOPE*x;
                x = fmaf(av.w, scale[kb+3], shift[kb+3]); av.w = (x >= 0.f) ? x : SLOPE*x;
            }
            As[ac4+0][r] = av.x;
            As[ac4+1][r] = av.y;
            As[ac4+2][r] = av.z;
            As[ac4+3][r] = av.w;
        }
#pragma unroll
        for (int i = 0; i < 2; i++) {
            int rr = br + i * 8;
            *(float4*)&Bs[rr][bc4] = *(const float4*)(B + (size_t)(kt + rr)*N + n0 + bc4);
        }
        __syncthreads();
#pragma unroll
        for (int kk = 0; kk < 16; kk++) {
            float4 a0 = *(const float4*)&As[kk][ty*4];
            float4 a1 = *(const float4*)&As[kk][64 + ty*4];
            float4 b0 = *(const float4*)&Bs[kk][tx*4];
            float4 b1 = *(const float4*)&Bs[kk][64 + tx*4];
            float a[8] = {a0.x,a0.y,a0.z,a0.w, a1.x,a1.y,a1.z,a1.w};
            float b[8] = {b0.x,b0.y,b0.z,b0.w, b1.x,b1.y,b1.z,b1.w};
#pragma unroll
            for (int i = 0; i < 8; i++)
#pragma unroll
                for (int j = 0; j < 8; j++) acc[i][j] = fmaf(a[i], b[j], acc[i][j]);
        }
        __syncthreads();
    }

    // ---- epilogue ----
    const int cA = n0 + tx*4;
    const int cB = n0 + 64 + tx*4;
    float colS[8], colQ[8];
#pragma unroll
    for (int j = 0; j < 8; j++) { colS[j] = 0.f; colQ[j] = 0.f; }

    float4 bias0 = *(const float4*)(bias + cA);
    float4 bias1 = *(const float4*)(bias + cB);

#pragma unroll
    for (int i = 0; i < 8; i++) {
        int m = m0 + (i >> 2)*64 + ty*4 + (i & 3);
        float v[8];
        v[0] = acc[i][0] + bias0.x; v[1] = acc[i][1] + bias0.y;
        v[2] = acc[i][2] + bias0.z; v[3] = acc[i][3] + bias0.w;
        v[4] = acc[i][4] + bias1.x; v[5] = acc[i][5] + bias1.y;
        v[6] = acc[i][6] + bias1.z; v[7] = acc[i][7] + bias1.w;
        float4 o0 = {v[0], v[1], v[2], v[3]};
        float4 o1 = {v[4], v[5], v[6], v[7]};
        *(float4*)(C + (size_t)m*N + cA) = o0;
        *(float4*)(C + (size_t)m*N + cB) = o1;
        if (MODE == 1) {
            int n = m >> 4;
            int jj = g_idx[m];
            float4 q0 = *(const float4*)(g_q  + (size_t)n *256 + cA);
            float4 q1 = *(const float4*)(g_q  + (size_t)n *256 + cB);
            float4 k0 = *(const float4*)(g_kv + (size_t)jj*512 + cA);
            float4 k1 = *(const float4*)(g_kv + (size_t)jj*512 + cB);
            float w[8];
            w[0] = q0.x - k0.x + v[0]; w[1] = q0.y - k0.y + v[1];
            w[2] = q0.z - k0.z + v[2]; w[3] = q0.w - k0.w + v[3];
            w[4] = q1.x - k1.x + v[4]; w[5] = q1.y - k1.y + v[5];
            w[6] = q1.z - k1.z + v[6]; w[7] = q1.w - k1.w + v[7];
            float4 w0f = {w[0], w[1], w[2], w[3]};
            float4 w1f = {w[4], w[5], w[6], w[7]};
            *(float4*)(g_w1 + (size_t)m*256 + cA) = w0f;
            *(float4*)(g_w1 + (size_t)m*256 + cB) = w1f;
#pragma unroll
            for (int j = 0; j < 8; j++) { colS[j] += w[j]; colQ[j] = fmaf(w[j], w[j], colQ[j]); }
        } else if (MODE == 2) {
#pragma unroll
            for (int j = 0; j < 8; j++) { colS[j] += v[j]; colQ[j] = fmaf(v[j], v[j], colQ[j]); }
        }
    }

    if (MODE != 0) {
        float* gS = (MODE == 1) ? g_s1 : g_s2;
        float* gQ = (MODE == 1) ? g_q1 : g_q2;
#pragma unroll
        for (int j = 0; j < 8; j++) {
            colS[j] += __shfl_xor_sync(0xffffffffu, colS[j], 16);
            colQ[j] += __shfl_xor_sync(0xffffffffu, colQ[j], 16);
        }
        if ((tid & 31) < 16) {
#pragma unroll
            for (int j = 0; j < 8; j++) {
                int col = n0 + (j >> 2)*64 + tx*4 + (j & 3);
                atomicAdd(&gS[col], colS[j]);
                atomicAdd(&gQ[col], colQ[j]);
            }
        }
    }
}

// ---------------- pe stage 1 + fused h-stats ----------------
__global__ void pe1_kernel(const float* __restrict__ xyz_i,
                           const float* __restrict__ xyz_last,
                           const float* __restrict__ t_i,
                           const float* __restrict__ t_last,
                           const float* __restrict__ wp1,
                           const float* __restrict__ bp1) {
    __shared__ float sred[64], qred[64];
    const int tid = threadIdx.x;
    if (tid < 64) { sred[tid] = 0.f; qred[tid] = 0.f; }
    __syncthreads();
    const int tid0 = blockIdx.x * 256 + tid;           // stride 512*256 = 131072 (mult of 64)
    const int c = tid0 & 63;
    const float dt = t_i[0] - t_last[0];
    const float w0 = wp1[c], w1v = wp1[64+c], w2v = wp1[128+c], w3 = wp1[192+c];
    const float bb = bp1[c];
    float s = 0.f, qq = 0.f;
    for (int gid = tid0; gid < NK*HDIM; gid += 512*256) {
        int sr = gid >> 6;
        int n = sr >> 4;
        int j = g_idx[sr];
        float px = xyz_i[j*3+0] - xyz_last[n*3+0];
        float py = xyz_i[j*3+1] - xyz_last[n*3+1];
        float pz = xyz_i[j*3+2] - xyz_last[n*3+2];
        float h = bb;
        h = fmaf(px, w0, h);
        h = fmaf(py, w1v, h);
        h = fmaf(pz, w2v, h);
        h = fmaf(dt, w3, h);
        g_h[gid] = h;
        s += h; qq = fmaf(h, h, qq);
    }
    atomicAdd(&sred[c], s);
    atomicAdd(&qred[c], qq);
    __syncthreads();
    if (tid < 64) {
        atomicAdd(&g_psum[tid], sred[tid]);
        atomicAdd(&g_pssq[tid], qred[tid]);
    }
}

// ---------------- BN finalize ----------------
__global__ void finalize_kernel(const float* __restrict__ gamma,
                                const float* __restrict__ beta,
                                float invM, int which) {
    int c = threadIdx.x;
    const float* gs = (which == 0) ? g_psum : ((which == 1) ? g_s1 : g_s2);
    const float* gq = (which == 0) ? g_pssq : ((which == 1) ? g_q1 : g_q2);
    float* sc = (which == 0) ? g_pscale : ((which == 1) ? g_sc1 : g_sc2);
    float* sh = (which == 0) ? g_pshift : ((which == 1) ? g_sh1 : g_sh2);
    float m = gs[c] * invM;
    float v = gq[c] * invM - m*m;
    float s = gamma[c] * rsqrtf(v + EPS);
    sc[c] = s;
    sh[c] = beta[c] - m*s;
}

// ---------------- final: bn2 + lrelu + softmax(K) + weighted v-sum ----------------
__global__ void final_kernel(float* __restrict__ out) {
    int n = blockIdx.x, c = threadIdx.x;
    __shared__ int sidx[KNN];
    if (c < KNN) sidx[c] = g_idx[n*KNN + c];
    __syncthreads();
    float sc = g_sc2[c], sh = g_sh2[c];
    float z[KNN];
    float m = -FLT_MAX;
#pragma unroll
    for (int k = 0; k < KNN; k++) {
        float x = g_w2[((size_t)n*KNN + k)*COUT + c];
        x = x*sc + sh;
        x = (x >= 0.f) ? x : SLOPE*x;
        z[k] = x;
        m = fmaxf(m, x);
    }
    float den = 0.f, num = 0.f;
#pragma unroll
    for (int k = 0; k < KNN; k++) {
        float e = __expf(z[k] - m);
        float v = g_kv[(size_t)sidx[k]*512 + 256 + c] + g_pe[((size_t)n*KNN + k)*COUT + c];
        den += e;
        num = fmaf(e, v, num);
    }
    out[(size_t)n*COUT + c] = num / den;
}

// ---------------- launch ----------------
extern "C" void kernel_launch(void* const* d_in, const int* in_sizes, int n_in,
                              void* d_out, int out_size) {
    const float* fea_i    = (const float*)d_in[0];
    const float* fea_last = (const float*)d_in[1];
    const float* xyz_i    = (const float*)d_in[2];
    const float* xyz_last = (const float*)d_in[3];
    const float* t_i      = (const float*)d_in[4];
    const float* t_last   = (const float*)d_in[5];
    const float* wp1 = (const float*)d_in[6];
    const float* bp1 = (const float*)d_in[7];
    const float* gp  = (const float*)d_in[8];
    const float* bp  = (const float*)d_in[9];
    const float* wp2 = (const float*)d_in[10];
    const float* bp2 = (const float*)d_in[11];
    const float* wq  = (const float*)d_in[12];
    const float* bq  = (const float*)d_in[13];
    const float* wk  = (const float*)d_in[14];
    const float* bk  = (const float*)d_in[15];
    const float* wv  = (const float*)d_in[16];
    const float* bv  = (const float*)d_in[17];
    const float* gw1 = (const float*)d_in[18];
    const float* bw1 = (const float*)d_in[19];
    const float* ww  = (const float*)d_in[20];
    const float* bw  = (const float*)d_in[21];
    const float* gw2 = (const float*)d_in[22];
    const float* bw2 = (const float*)d_in[23];
    float* out = (float*)d_out;

    void* p;
    cudaGetSymbolAddress(&p, g_q);   float* p_q   = (float*)p;
    cudaGetSymbolAddress(&p, g_kv);  float* p_kv  = (float*)p;
    cudaGetSymbolAddress(&p, g_wkv); float* p_wkv = (float*)p;
    cudaGetSymbolAddress(&p, g_bkv); float* p_bkv = (float*)p;
    cudaGetSymbolAddress(&p, g_h);   float* p_h   = (float*)p;
    cudaGetSymbolAddress(&p, g_pe);  float* p_pe  = (float*)p;
    cudaGetSymbolAddress(&p, g_w1);  float* p_w1  = (float*)p;
    cudaGetSymbolAddress(&p, g_w2);  float* p_w2  = (float*)p;

    zero_stats_kernel<<<1, 256>>>();
    concat_kv_kernel<<<(CIN*512)/256, 256>>>(wk, wv, bk, bv);

    // 1) kNN
    knn_kernel<<<N_PTS/QPB, 256>>>(xyz_i, xyz_last);

    // 2) projections
    dim3 gQ(COUT/128, N_PTS/128);
    sgemm_kernel<0><<<gQ, 256>>>(fea_last, wq, bq, p_q, N_PTS, COUT, CIN);
    dim3 gKV(512/128, N_PTS/128);
    sgemm_kernel<0><<<gKV, 256>>>(fea_i, p_wkv, p_bkv, p_kv, N_PTS, 512, CIN);

    // 3) pe stage 1 (+h stats), BN finalize
    pe1_kernel<<<512, 256>>>(xyz_i, xyz_last, t_i, t_last, wp1, bp1);
    finalize_kernel<<<1, HDIM>>>(gp, bp, 1.f/(float)NK, 0);

    // 4) pe GEMM + fused w1 construction + BN1 stats
    dim3 gBig(COUT/128, NK/128);
    sgemm_kernel<1><<<gBig, 256>>>(p_h, wp2, bp2, p_pe, NK, COUT, HDIM);
    finalize_kernel<<<1, COUT>>>(gw1, bw1, 1.f/(float)NK, 1);

    // 5) w2 GEMM + fused BN2 stats
    sgemm_kernel<2><<<gBig, 256>>>(p_w1, ww, bw, p_w2, NK, COUT, CIN);
    finalize_kernel<<<1, COUT>>>(gw2, bw2, 1.f/(float)NK, 2);

    // 6) softmax over K + weighted v-sum
    final_kernel<<<N_PTS, COUT>>>(out);
}

// round 4
// speedup vs baseline: 1.6395x; 1.3268x over previous
#include <cuda_runtime.h>
#include <cuda_bf16.h>
#include <cstdint>
#include <cfloat>

#define N_PTS 8192
#define KNN   16
#define CIN   256
#define COUT  256
#define NK    (N_PTS*KNN)       // 131072
#define HDIM  64
#define SLOPE 0.01f
#define EPS   1e-5f
#define TILE  1024
#define QPB   8
#define ASTR  40                // A smem row stride in halves (80B, conflict-free ldsm)
#define BSTR  136               // B smem row stride in halves (272B, conflict-free ldsm)

// ---------------- device scratch (static, allocation-free) ----------------
__device__ int   g_idx[NK];
__device__ float g_q  [N_PTS*COUT];
__device__ float g_kv [N_PTS*512];     // [kf | vf]
__device__ float g_wkv[CIN*512];       // [wk | wv]
__device__ float g_bkv[512];
__device__ float g_pe [NK*COUT];       // 128 MB
__device__ float g_w1 [NK*COUT];       // 128 MB
__device__ float g_w2 [NK*COUT];       // 128 MB
__device__ float g_m[9];               // pe4 moments: x,y,z,xx,yy,zz,xy,xz,yz
__device__ float g_pscale[HDIM], g_pshift[HDIM];
__device__ float g_s1[COUT], g_q1[COUT], g_sc1[COUT], g_sh1[COUT];
__device__ float g_s2[COUT], g_q2[COUT], g_sc2[COUT], g_sh2[COUT];

// ---------------- PTX helpers ----------------
__device__ __forceinline__ uint32_t su32(const void* p) {
    return (uint32_t)__cvta_generic_to_shared(p);
}
__device__ __forceinline__ void ldsm4(uint32_t r[4], uint32_t a) {
    asm volatile("ldmatrix.sync.aligned.m8n8.x4.shared.b16 {%0,%1,%2,%3}, [%4];"
        : "=r"(r[0]), "=r"(r[1]), "=r"(r[2]), "=r"(r[3]) : "r"(a));
}
__device__ __forceinline__ void ldsm4t(uint32_t r[4], uint32_t a) {
    asm volatile("ldmatrix.sync.aligned.m8n8.x4.trans.shared.b16 {%0,%1,%2,%3}, [%4];"
        : "=r"(r[0]), "=r"(r[1]), "=r"(r[2]), "=r"(r[3]) : "r"(a));
}
__device__ __forceinline__ void mma16816(float c[4], const uint32_t a[4], const uint32_t b[2]) {
    asm volatile("mma.sync.aligned.m16n8k16.row.col.f32.bf16.bf16.f32 "
        "{%0,%1,%2,%3}, {%4,%5,%6,%7}, {%8,%9}, {%0,%1,%2,%3};"
        : "+f"(c[0]), "+f"(c[1]), "+f"(c[2]), "+f"(c[3])
        : "r"(a[0]), "r"(a[1]), "r"(a[2]), "r"(a[3]), "r"(b[0]), "r"(b[1]));
}
// split x into hi+lo bf16; pack two elements into u32s
__device__ __forceinline__ uint32_t split_pack(float x0, float x1, uint32_t& lo) {
    __nv_bfloat16 h0 = __float2bfloat16_rn(x0);
    __nv_bfloat16 h1 = __float2bfloat16_rn(x1);
    __nv_bfloat16 l0 = __float2bfloat16_rn(x0 - __bfloat162float(h0));
    __nv_bfloat16 l1 = __float2bfloat16_rn(x1 - __bfloat162float(h1));
    uint16_t uh0 = *(uint16_t*)&h0, uh1 = *(uint16_t*)&h1;
    uint16_t ul0 = *(uint16_t*)&l0, ul1 = *(uint16_t*)&l1;
    lo = (uint32_t)ul0 | ((uint32_t)ul1 << 16);
    return (uint32_t)uh0 | ((uint32_t)uh1 << 16);
}

// ---------------- zero stats ----------------
__global__ void zero_stats_kernel() {
    int t = threadIdx.x;
    if (t < 9) g_m[t] = 0.f;
    if (t < COUT) { g_s1[t] = 0.f; g_q1[t] = 0.f; g_s2[t] = 0.f; g_q2[t] = 0.f; }
}

// ---------------- weight concat for fused kf/vf projection ----------------
__global__ void concat_kv_kernel(const float* __restrict__ wk, const float* __restrict__ wv,
                                 const float* __restrict__ bk, const float* __restrict__ bv) {
    int i = blockIdx.x * 256 + threadIdx.x;
    int k = i >> 9, c = i & 511;
    g_wkv[i] = (c < 256) ? wk[k*256 + c] : wv[k*256 + c - 256];
    if (i < 512) g_bkv[i] = (i < 256) ? bk[i] : bv[i - 256];
}

// ---------------- kNN (bit-identical to passing version) ----------------
__device__ __forceinline__ float norm3_ref(float x, float y, float z) {
    return __fadd_rn(__fadd_rn(__fmul_rn(x, x), __fmul_rn(y, y)), __fmul_rn(z, z));
}

__global__ void knn_kernel(const float* __restrict__ xyz_i,
                           const float* __restrict__ xyz_last) {
    __shared__ float sx[TILE], sy[TILE], sz[TILE], sn2[TILE];
    __shared__ float ld[QPB][KNN][32];
    __shared__ int   li[QPB][KNN][32];
    const int tid = threadIdx.x;
    const int w = tid >> 5, lane = tid & 31;
    const int q = blockIdx.x * QPB + w;
    const float qx = xyz_last[q*3+0];
    const float qy = xyz_last[q*3+1];
    const float qz = xyz_last[q*3+2];
    const float nq = norm3_ref(qx, qy, qz);
#pragma unroll
    for (int j = 0; j < KNN; j++) { ld[w][j][lane] = FLT_MAX; li[w][j][lane] = 0x7fffffff; }

    for (int t0 = 0; t0 < N_PTS; t0 += TILE) {
        __syncthreads();
        for (int p = tid; p < TILE; p += 256) {
            float x = xyz_i[(t0+p)*3+0];
            float y = xyz_i[(t0+p)*3+1];
            float z = xyz_i[(t0+p)*3+2];
            sx[p] = x; sy[p] = y; sz[p] = z;
            sn2[p] = norm3_ref(x, y, z);
        }
        __syncthreads();
        for (int i = lane; i < TILE; i += 32) {
            float px = sx[i], py = sy[i], pz = sz[i];
            float t = __fmul_rn(qx, px);
            t = __fmaf_rn(qy, py, t);
            t = __fmaf_rn(qz, pz, t);
            float d2 = __fsub_rn(__fadd_rn(nq, sn2[i]), __fmul_rn(2.0f, t));
            if (d2 < ld[w][KNN-1][lane]) {
                int gi = t0 + i;
                int j = KNN - 1;
                while (j > 0 && ld[w][j-1][lane] > d2) {
                    ld[w][j][lane] = ld[w][j-1][lane];
                    li[w][j][lane] = li[w][j-1][lane];
                    j--;
                }
                ld[w][j][lane] = d2;
                li[w][j][lane] = gi;
            }
        }
    }
    int pos = 0;
    for (int r = 0; r < KNN; r++) {
        float v = (pos < KNN) ? ld[w][pos][lane] : FLT_MAX;
        int  gi = (pos < KNN) ? li[w][pos][lane] : 0x7fffffff;
        int  owner = lane;
#pragma unroll
        for (int off = 16; off > 0; off >>= 1) {
            float v2  = __shfl_xor_sync(0xffffffffu, v, off);
            int   g2  = __shfl_xor_sync(0xffffffffu, gi, off);
            int   o2  = __shfl_xor_sync(0xffffffffu, owner, off);
            if (v2 < v || (v2 == v && g2 < gi)) { v = v2; gi = g2; owner = o2; }
        }
        if (lane == 0) g_idx[q*KNN + r] = gi;
        if (lane == owner) pos++;
    }
}

// ---------------- pe4 moments (analytic BN stats for pe layer) ----------------
__global__ void moments_kernel(const float* __restrict__ xyz_i,
                               const float* __restrict__ xyz_last) {
    float a0=0,a1=0,a2=0,a3=0,a4=0,a5=0,a6=0,a7=0,a8=0;
    for (int s = blockIdx.x * 256 + threadIdx.x; s < NK; s += gridDim.x * 256) {
        int n = s >> 4;
        int j = g_idx[s];
        float x = xyz_i[j*3+0] - xyz_last[n*3+0];
        float y = xyz_i[j*3+1] - xyz_last[n*3+1];
        float z = xyz_i[j*3+2] - xyz_last[n*3+2];
        a0 += x; a1 += y; a2 += z;
        a3 = fmaf(x,x,a3); a4 = fmaf(y,y,a4); a5 = fmaf(z,z,a5);
        a6 = fmaf(x,y,a6); a7 = fmaf(x,z,a7); a8 = fmaf(y,z,a8);
    }
    float v[9] = {a0,a1,a2,a3,a4,a5,a6,a7,a8};
#pragma unroll
    for (int i = 0; i < 9; i++) {
#pragma unroll
        for (int off = 16; off > 0; off >>= 1)
            v[i] += __shfl_xor_sync(0xffffffffu, v[i], off);
    }
    if ((threadIdx.x & 31) == 0) {
#pragma unroll
        for (int i = 0; i < 9; i++) atomicAdd(&g_m[i], v[i]);
    }
}

__global__ void finalize_pe_kernel(const float* __restrict__ gp, const float* __restrict__ bp_,
                                   const float* __restrict__ wp1, const float* __restrict__ bp1,
                                   const float* __restrict__ t_i, const float* __restrict__ t_last) {
    int c = threadIdx.x;                 // 64
    float inv = 1.f / (float)NK;
    float mx = g_m[0]*inv, my = g_m[1]*inv, mz = g_m[2]*inv;
    float exx = g_m[3]*inv, eyy = g_m[4]*inv, ezz = g_m[5]*inv;
    float exy = g_m[6]*inv, exz = g_m[7]*inv, eyz = g_m[8]*inv;
    float w0 = wp1[c], w1 = wp1[64+c], w2 = wp1[128+c], w3 = wp1[192+c];
    float a  = bp1[c] + w3*(t_i[0] - t_last[0]);
    float lm = w0*mx + w1*my + w2*mz;
    float mean = a + lm;
    float e2 = a*a + 2.f*a*lm
             + w0*w0*exx + w1*w1*eyy + w2*w2*ezz
             + 2.f*(w0*w1*exy + w0*w2*exz + w1*w2*eyz);
    float var = e2 - mean*mean;
    float s = gp[c] * rsqrtf(var + EPS);
    g_pscale[c] = s;
    g_pshift[c] = bp_[c] - mean*s;
}

// ---------------- BN finalize (w1 / w2) ----------------
__global__ void finalize_kernel(const float* __restrict__ gamma,
                                const float* __restrict__ beta,
                                float invM, int which) {
    int c = threadIdx.x;
    const float* gs = (which == 1) ? g_s1 : g_s2;
    const float* gq = (which == 1) ? g_q1 : g_q2;
    float* sc = (which == 1) ? g_sc1 : g_sc2;
    float* sh = (which == 1) ? g_sh1 : g_sh2;
    float m = gs[c] * invM;
    float v = gq[c] * invM - m*m;
    float s = gamma[c] * rsqrtf(v + EPS);
    sc[c] = s;
    sh[c] = beta[c] - m*s;
}

// ---------------- tensor-core GEMM (bf16 hi/lo split, fused epilogues) ----------
// C[M,N] = f(A)[M,K] @ B[K,N] + bias
// MODE 0: plain
// MODE 1 (GENA): A generated from xyz: lrelu(bn(pe4@wp1+bp1)); epilogue writes C(=pe)
//                AND g_w1 = q - kf[idx] + pe, accumulating BN1 stats of w1
// MODE 2: f = lrelu(x*sc1+sh1); epilogue writes C(=w2), accumulates BN2 stats
template<int MODE, bool GENA>
__global__ __launch_bounds__(256, 1)
void mma_gemm(const float* __restrict__ A, const float* __restrict__ B,
              const float* __restrict__ bias, float* __restrict__ C,
              int M, int N, int K,
              const float* __restrict__ xyz_i, const float* __restrict__ xyz_last,
              const float* __restrict__ t_i, const float* __restrict__ t_last,
              const float* __restrict__ wp1, const float* __restrict__ bp1) {
    __shared__ __align__(16) uint16_t Ah[128*ASTR], Al[128*ASTR];
    __shared__ __align__(16) uint16_t Bh[32*BSTR], Bl[32*BSTR];
    __shared__ float spx[128], spy[128], spz[128];
    __shared__ float swp[256], sbp[64], sps[64], ssh[64];

    const int tid = threadIdx.x;
    const int lane = tid & 31, wid = tid >> 5;
    const int wm = wid >> 1, wn = wid & 1;
    const int m0 = blockIdx.y * 128, n0 = blockIdx.x * 128;

    float dtv = 0.f;
    if (GENA) {
        if (tid < 128) {
            int m = m0 + tid;
            int n = m >> 4;
            int j = g_idx[m];
            spx[tid] = xyz_i[j*3+0] - xyz_last[n*3+0];
            spy[tid] = xyz_i[j*3+1] - xyz_last[n*3+1];
            spz[tid] = xyz_i[j*3+2] - xyz_last[n*3+2];
        }
        swp[tid] = wp1[tid];
        if (tid < 64) { sbp[tid] = bp1[tid]; sps[tid] = g_pscale[tid]; ssh[tid] = g_pshift[tid]; }
        dtv = t_i[0] - t_last[0];
        __syncthreads();
    }

    float acc[2][8][4];
#pragma unroll
    for (int i = 0; i < 2; i++)
#pragma unroll
        for (int j = 0; j < 8; j++)
#pragma unroll
            for (int e = 0; e < 4; e++) acc[i][j][e] = 0.f;

    const int arow = tid >> 1, ak = (tid & 1) * 16;
    const int brow = tid >> 3, bn = (tid & 7) * 16;

    float4 areg[4], breg[4];
    if (!GENA) {
#pragma unroll
        for (int u = 0; u < 4; u++)
            areg[u] = *(const float4*)(A + (size_t)(m0 + arow)*K + ak + u*4);
    }
#pragma unroll
    for (int u = 0; u < 4; u++)
        breg[u] = *(const float4*)(B + (size_t)brow*N + n0 + bn + u*4);

    const uint32_t AhB = su32(Ah), AlB = su32(Al), BhB = su32(Bh), BlB = su32(Bl);
    uint32_t a_off[2], b_off[4];
#pragma unroll
    for (int mt = 0; mt < 2; mt++)
        a_off[mt] = (uint32_t)(((wm*32 + mt*16 + (lane & 15))*ASTR + (lane >> 4)*8) * 2);
#pragma unroll
    for (int p = 0; p < 4; p++)
        b_off[p] = (uint32_t)(((lane & 15)*BSTR + wn*64 + p*16 + (lane >> 4)*8) * 2);

    for (int kt = 0; kt < K; kt += 32) {
        // ---- store stage kt into smem (split bf16) ----
        if (GENA) {
            float px = spx[arow], py = spy[arow], pz = spz[arow];
#pragma unroll
            for (int u = 0; u < 4; u++) {
                float h[4];
#pragma unroll
                for (int e = 0; e < 4; e++) {
                    int c = kt + ak + u*4 + e;
                    float hh = sbp[c];
                    hh = fmaf(px, swp[c],     hh);
                    hh = fmaf(py, swp[64+c],  hh);
                    hh = fmaf(pz, swp[128+c], hh);
                    hh = fmaf(dtv, swp[192+c], hh);
                    float x = fmaf(hh, sps[c], ssh[c]);
                    h[e] = (x >= 0.f) ? x : SLOPE*x;
                }
                uint32_t lo0, lo1;
                uint32_t hi0 = split_pack(h[0], h[1], lo0);
                uint32_t hi1 = split_pack(h[2], h[3], lo1);
                int idx = arow*ASTR + ak + u*4;
                *(uint2*)&Ah[idx] = make_uint2(hi0, hi1);
                *(uint2*)&Al[idx] = make_uint2(lo0, lo1);
            }
        } else {
#pragma unroll
            for (int u = 0; u < 4; u++) {
                float4 v = areg[u];
                if (MODE == 2) {
                    int c = kt + ak + u*4;
                    float x;
                    x = fmaf(v.x, g_sc1[c+0], g_sh1[c+0]); v.x = (x >= 0.f) ? x : SLOPE*x;
                    x = fmaf(v.y, g_sc1[c+1], g_sh1[c+1]); v.y = (x >= 0.f) ? x : SLOPE*x;
                    x = fmaf(v.z, g_sc1[c+2], g_sh1[c+2]); v.z = (x >= 0.f) ? x : SLOPE*x;
                    x = fmaf(v.w, g_sc1[c+3], g_sh1[c+3]); v.w = (x >= 0.f) ? x : SLOPE*x;
                }
                uint32_t lo0, lo1;
                uint32_t hi0 = split_pack(v.x, v.y, lo0);
                uint32_t hi1 = split_pack(v.z, v.w, lo1);
                int idx = arow*ASTR + ak + u*4;
                *(uint2*)&Ah[idx] = make_uint2(hi0, hi1);
                *(uint2*)&Al[idx] = make_uint2(lo0, lo1);
            }
        }
#pragma unroll
        for (int u = 0; u < 4; u++) {
            float4 v = breg[u];
            uint32_t lo0, lo1;
            uint32_t hi0 = split_pack(v.x, v.y, lo0);
            uint32_t hi1 = split_pack(v.z, v.w, lo1);
            int idx = brow*BSTR + bn + u*4;
            *(uint2*)&Bh[idx] = make_uint2(hi0, hi1);
            *(uint2*)&Bl[idx] = make_uint2(lo0, lo1);
        }
        __syncthreads();

        // ---- prefetch next stage ----
        if (kt + 32 < K) {
            if (!GENA) {
#pragma unroll
                for (int u = 0; u < 4; u++)
                    areg[u] = *(const float4*)(A + (size_t)(m0 + arow)*K + kt + 32 + ak + u*4);
            }
#pragma unroll
            for (int u = 0; u < 4; u++)
                breg[u] = *(const float4*)(B + (size_t)(kt + 32 + brow)*N + n0 + bn + u*4);
        }

        // ---- compute ----
#pragma unroll
        for (int ko = 0; ko < 2; ko++) {
            uint32_t ah[2][4], al_[2][4];
#pragma unroll
            for (int mt = 0; mt < 2; mt++) {
                ldsm4(ah[mt],  AhB + a_off[mt] + ko*32);
                ldsm4(al_[mt], AlB + a_off[mt] + ko*32);
            }
            uint32_t bh[8][2], bl[8][2];
#pragma unroll
            for (int p = 0; p < 4; p++) {
                uint32_t r[4];
                ldsm4t(r, BhB + b_off[p] + ko*16*BSTR*2);
                bh[2*p][0] = r[0]; bh[2*p][1] = r[1];
                bh[2*p+1][0] = r[2]; bh[2*p+1][1] = r[3];
                ldsm4t(r, BlB + b_off[p] + ko*16*BSTR*2);
                bl[2*p][0] = r[0]; bl[2*p][1] = r[1];
                bl[2*p+1][0] = r[2]; bl[2*p+1][1] = r[3];
            }
#pragma unroll
            for (int mt = 0; mt < 2; mt++)
#pragma unroll
                for (int nt = 0; nt < 8; nt++) {
                    mma16816(acc[mt][nt], ah[mt],  bh[nt]);
                    mma16816(acc[mt][nt], ah[mt],  bl[nt]);
                    mma16816(acc[mt][nt], al_[mt], bh[nt]);
                }
        }
        __syncthreads();
    }

    // ---- epilogue ----
    float colS[16], colQ[16];
    if (MODE != 0) {
#pragma unroll
        for (int i = 0; i < 16; i++) { colS[i] = 0.f; colQ[i] = 0.f; }
    }
#pragma unroll
    for (int mt = 0; mt < 2; mt++) {
        int r0 = m0 + wm*32 + mt*16 + (lane >> 2);
        int r1 = r0 + 8;
        int j0 = 0, j1 = 0, p0 = 0, p1 = 0;
        if (MODE == 1) {
            j0 = g_idx[r0]; j1 = g_idx[r1];
            p0 = r0 >> 4;   p1 = r1 >> 4;
        }
#pragma unroll
        for (int nt = 0; nt < 8; nt++) {
            int c = n0 + wn*64 + nt*8 + (lane & 3)*2;
            float2 bb = *(const float2*)(bias + c);
            float v00 = acc[mt][nt][0] + bb.x, v01 = acc[mt][nt][1] + bb.y;
            float v10 = acc[mt][nt][2] + bb.x, v11 = acc[mt][nt][3] + bb.y;
            *(float2*)(C + (size_t)r0*N + c) = make_float2(v00, v01);
            *(float2*)(C + (size_t)r1*N + c) = make_float2(v10, v11);
            if (MODE == 1) {
                float2 q0 = *(const float2*)(g_q  + (size_t)p0*256 + c);
                float2 q1 = *(const float2*)(g_q  + (size_t)p1*256 + c);
                float2 k0 = *(const float2*)(g_kv + (size_t)j0*512 + c);
                float2 k1 = *(const float2*)(g_kv + (size_t)j1*512 + c);
                float w00 = q0.x - k0.x + v00, w01 = q0.y - k0.y + v01;
                float w10 = q1.x - k1.x + v10, w11 = q1.y - k1.y + v11;
                *(float2*)(g_w1 + (size_t)r0*256 + c) = make_float2(w00, w01);
                *(float2*)(g_w1 + (size_t)r1*256 + c) = make_float2(w10, w11);
                colS[nt*2+0] += w00 + w10;  colS[nt*2+1] += w01 + w11;
                colQ[nt*2+0] += w00*w00 + w10*w10;
                colQ[nt*2+1] += w01*w01 + w11*w11;
            } else if (MODE == 2) {
                colS[nt*2+0] += v00 + v10;  colS[nt*2+1] += v01 + v11;
                colQ[nt*2+0] += v00*v00 + v10*v10;
                colQ[nt*2+1] += v01*v01 + v11*v11;
            }
        }
    }
    if (MODE != 0) {
        float* gS = (MODE == 1) ? g_s1 : g_s2;
        float* gQ = (MODE == 1) ? g_q1 : g_q2;
#pragma unroll
        for (int i = 0; i < 16; i++) {
#pragma unroll
            for (int off = 4; off <= 16; off <<= 1) {
                colS[i] += __shfl_xor_sync(0xffffffffu, colS[i], off);
                colQ[i] += __shfl_xor_sync(0xffffffffu, colQ[i], off);
            }
        }
        if (lane < 4) {
#pragma unroll
            for (int nt = 0; nt < 8; nt++) {
#pragma unroll
                for (int j = 0; j < 2; j++) {
                    int c = n0 + wn*64 + nt*8 + lane*2 + j;
                    atomicAdd(&gS[c], colS[nt*2+j]);
                    atomicAdd(&gQ[c], colQ[nt*2+j]);
                }
            }
        }
    }
}

// ---------------- final: bn2 + lrelu + softmax(K) + weighted v-sum ----------------
__global__ void final_kernel(float* __restrict__ out) {
    int n = blockIdx.x, c = threadIdx.x;
    __shared__ int sidx[KNN];
    if (c < KNN) sidx[c] = g_idx[n*KNN + c];
    __syncthreads();
    float sc = g_sc2[c], sh = g_sh2[c];
    float z[KNN];
    float m = -FLT_MAX;
#pragma unroll
    for (int k = 0; k < KNN; k++) {
        float x = g_w2[((size_t)n*KNN + k)*COUT + c];
        x = x*sc + sh;
        x = (x >= 0.f) ? x : SLOPE*x;
        z[k] = x;
        m = fmaxf(m, x);
    }
    float den = 0.f, num = 0.f;
#pragma unroll
    for (int k = 0; k < KNN; k++) {
        float e = __expf(z[k] - m);
        float v = g_kv[(size_t)sidx[k]*512 + 256 + c] + g_pe[((size_t)n*KNN + k)*COUT + c];
        den += e;
        num = fmaf(e, v, num);
    }
    out[(size_t)n*COUT + c] = num / den;
}

// ---------------- launch ----------------
extern "C" void kernel_launch(void* const* d_in, const int* in_sizes, int n_in,
                              void* d_out, int out_size) {
    const float* fea_i    = (const float*)d_in[0];
    const float* fea_last = (const float*)d_in[1];
    const float* xyz_i    = (const float*)d_in[2];
    const float* xyz_last = (const float*)d_in[3];
    const float* t_i      = (const float*)d_in[4];
    const float* t_last   = (const float*)d_in[5];
    const float* wp1 = (const float*)d_in[6];
    const float* bp1 = (const float*)d_in[7];
    const float* gp  = (const float*)d_in[8];
    const float* bp  = (const float*)d_in[9];
    const float* wp2 = (const float*)d_in[10];
    const float* bp2 = (const float*)d_in[11];
    const float* wq  = (const float*)d_in[12];
    const float* bq  = (const float*)d_in[13];
    const float* wk  = (const float*)d_in[14];
    const float* bk  = (const float*)d_in[15];
    const float* wv  = (const float*)d_in[16];
    const float* bv  = (const float*)d_in[17];
    const float* gw1 = (const float*)d_in[18];
    const float* bw1 = (const float*)d_in[19];
    const float* ww  = (const float*)d_in[20];
    const float* bw  = (const float*)d_in[21];
    const float* gw2 = (const float*)d_in[22];
    const float* bw2 = (const float*)d_in[23];
    float* out = (float*)d_out;

    void* p;
    cudaGetSymbolAddress(&p, g_q);   float* p_q   = (float*)p;
    cudaGetSymbolAddress(&p, g_kv);  float* p_kv  = (float*)p;
    cudaGetSymbolAddress(&p, g_wkv); float* p_wkv = (float*)p;
    cudaGetSymbolAddress(&p, g_bkv); float* p_bkv = (float*)p;
    cudaGetSymbolAddress(&p, g_pe);  float* p_pe  = (float*)p;
    cudaGetSymbolAddress(&p, g_w1);  float* p_w1  = (float*)p;
    cudaGetSymbolAddress(&p, g_w2);  float* p_w2  = (float*)p;

    zero_stats_kernel<<<1, 256>>>();
    concat_kv_kernel<<<(CIN*512)/256, 256>>>(wk, wv, bk, bv);

    // 1) kNN
    knn_kernel<<<N_PTS/QPB, 256>>>(xyz_i, xyz_last);

    // 2) projections (tensor core)
    dim3 gQ(COUT/128, N_PTS/128);
    mma_gemm<0,false><<<gQ, 256>>>(fea_last, wq, bq, p_q, N_PTS, COUT, CIN,
                                   nullptr, nullptr, nullptr, nullptr, nullptr, nullptr);
    dim3 gKV(512/128, N_PTS/128);
    mma_gemm<0,false><<<gKV, 256>>>(fea_i, p_wkv, p_bkv, p_kv, N_PTS, 512, CIN,
                                    nullptr, nullptr, nullptr, nullptr, nullptr, nullptr);

    // 3) analytic pe-BN stats (needs g_idx)
    moments_kernel<<<64, 256>>>(xyz_i, xyz_last);
    finalize_pe_kernel<<<1, HDIM>>>(gp, bp, wp1, bp1, t_i, t_last);

    // 4) pe GEMM (A generated from xyz) + fused w1 construction + BN1 stats
    dim3 gBig(COUT/128, NK/128);
    mma_gemm<1,true><<<gBig, 256>>>(nullptr, wp2, bp2, p_pe, NK, COUT, HDIM,
                                    xyz_i, xyz_last, t_i, t_last, wp1, bp1);
    finalize_kernel<<<1, COUT>>>(gw1, bw1, 1.f/(float)NK, 1);

    // 5) w2 GEMM + fused BN2 stats
    mma_gemm<2,false><<<gBig, 256>>>(p_w1, ww, bw, p_w2, NK, COUT, CIN,
                                     nullptr, nullptr, nullptr, nullptr, nullptr, nullptr);
    finalize_kernel<<<1, COUT>>>(gw2, bw2, 1.f/(float)NK, 2);

    // 6) softmax over K + weighted v-sum
    final_kernel<<<N_PTS, COUT>>>(out);
}

// round 6
// speedup vs baseline: 1.8236x; 1.1123x over previous
#include <cuda_runtime.h>
#include <cuda_bf16.h>
#include <cstdint>
#include <cfloat>

#define N_PTS 8192
#define KNN   16
#define CIN   256
#define COUT  256
#define NK    (N_PTS*KNN)       // 131072
#define HDIM  64
#define SLOPE 0.01f
#define EPS   1e-5f
#define TILE  1024
#define QPB   8
#define ASTR  40                // A smem row stride in halves
#define BSTR  136               // B smem row stride in halves

// weight-split buffer offsets (natural [K,N] layout, bf16 hi/lo)
#define OQ   0
#define OKV  65536              // 256*256
#define OP2  196608             // + 256*512
#define OW   212992             // + 64*256
#define TOTW 278528             // + 256*256

// ---------------- device scratch (static, allocation-free) ----------------
__device__ int      g_idx[NK];
__device__ float    g_q  [N_PTS*COUT];
__device__ float    g_kv [N_PTS*512];     // [kf | vf]
__device__ float    g_bkv[512];
__device__ uint16_t g_bth[TOTW];          // weights bf16 hi, [K,N]
__device__ uint16_t g_btl[TOTW];          // weights bf16 lo, [K,N]
__device__ float    g_w1 [NK*COUT];
__device__ float    g_w2 [NK*COUT];
__device__ float    g_m[9];               // pe4 moments
__device__ float    g_pscale[HDIM], g_pshift[HDIM];
__device__ float    g_s1[COUT], g_q1[COUT], g_sc1[COUT], g_sh1[COUT];
__device__ float    g_s2[COUT], g_q2[COUT], g_sc2[COUT], g_sh2[COUT];

// ---------------- PTX helpers ----------------
__device__ __forceinline__ uint32_t su32(const void* p) {
    return (uint32_t)__cvta_generic_to_shared(p);
}
__device__ __forceinline__ void ldsm4(uint32_t r[4], uint32_t a) {
    asm volatile("ldmatrix.sync.aligned.m8n8.x4.shared.b16 {%0,%1,%2,%3}, [%4];"
        : "=r"(r[0]), "=r"(r[1]), "=r"(r[2]), "=r"(r[3]) : "r"(a));
}
__device__ __forceinline__ void ldsm4t(uint32_t r[4], uint32_t a) {
    asm volatile("ldmatrix.sync.aligned.m8n8.x4.trans.shared.b16 {%0,%1,%2,%3}, [%4];"
        : "=r"(r[0]), "=r"(r[1]), "=r"(r[2]), "=r"(r[3]) : "r"(a));
}
__device__ __forceinline__ void mma16816(float c[4], const uint32_t a[4], const uint32_t b[2]) {
    asm volatile("mma.sync.aligned.m16n8k16.row.col.f32.bf16.bf16.f32 "
        "{%0,%1,%2,%3}, {%4,%5,%6,%7}, {%8,%9}, {%0,%1,%2,%3};"
        : "+f"(c[0]), "+f"(c[1]), "+f"(c[2]), "+f"(c[3])
        : "r"(a[0]), "r"(a[1]), "r"(a[2]), "r"(a[3]), "r"(b[0]), "r"(b[1]));
}
__device__ __forceinline__ void split1(float x, uint16_t& hi, uint16_t& lo) {
    __nv_bfloat16 h = __float2bfloat16_rn(x);
    __nv_bfloat16 l = __float2bfloat16_rn(x - __bfloat162float(h));
    hi = *(uint16_t*)&h; lo = *(uint16_t*)&l;
}
__device__ __forceinline__ void pack8(const float* v, uint4& H, uint4& L) {
    uint16_t h[8], l[8];
#pragma unroll
    for (int i = 0; i < 8; i++) split1(v[i], h[i], l[i]);
    H.x = (uint32_t)h[0] | ((uint32_t)h[1] << 16);
    H.y = (uint32_t)h[2] | ((uint32_t)h[3] << 16);
    H.z = (uint32_t)h[4] | ((uint32_t)h[5] << 16);
    H.w = (uint32_t)h[6] | ((uint32_t)h[7] << 16);
    L.x = (uint32_t)l[0] | ((uint32_t)l[1] << 16);
    L.y = (uint32_t)l[2] | ((uint32_t)l[3] << 16);
    L.z = (uint32_t)l[4] | ((uint32_t)l[5] << 16);
    L.w = (uint32_t)l[6] | ((uint32_t)l[7] << 16);
}

// ---------------- zero stats ----------------
__global__ void zero_stats_kernel() {
    int t = threadIdx.x;
    if (t < 9) g_m[t] = 0.f;
    if (t < COUT) { g_s1[t] = 0.f; g_q1[t] = 0.f; g_s2[t] = 0.f; g_q2[t] = 0.f; }
}

// ---------------- bias concat + weight split (bf16 hi/lo, [K,N]) ----------
__global__ void bias_kv_kernel(const float* __restrict__ bk, const float* __restrict__ bv) {
    int i = blockIdx.x * 256 + threadIdx.x;
    if (i < 512) g_bkv[i] = (i < 256) ? bk[i] : bv[i - 256];
}

__global__ void split_w_kernel(const float* __restrict__ wq,
                               const float* __restrict__ wk, const float* __restrict__ wv,
                               const float* __restrict__ wp2, const float* __restrict__ ww) {
    int i = blockIdx.x * 256 + threadIdx.x;
    if (i >= TOTW) return;
    float val;
    if (i < OKV) {                       // wq [256,256]
        val = wq[i];
    } else if (i < OP2) {                // wkv [256,512]: row k = [wk_k | wv_k]
        int j = i - OKV, k = j >> 9, n = j & 511;
        val = (n < 256) ? wk[k*256 + n] : wv[k*256 + (n - 256)];
    } else if (i < OW) {                 // wp2 [64,256]
        val = wp2[i - OP2];
    } else {                             // ww [256,256]
        val = ww[i - OW];
    }
    uint16_t h, l;
    split1(val, h, l);
    g_bth[i] = h; g_btl[i] = l;
}

// ---------------- kNN (bit-identical to passing version) ----------------
__device__ __forceinline__ float norm3_ref(float x, float y, float z) {
    return __fadd_rn(__fadd_rn(__fmul_rn(x, x), __fmul_rn(y, y)), __fmul_rn(z, z));
}

__global__ void knn_kernel(const float* __restrict__ xyz_i,
                           const float* __restrict__ xyz_last) {
    __shared__ float sx[TILE], sy[TILE], sz[TILE], sn2[TILE];
    __shared__ float ld[QPB][KNN][32];
    __shared__ int   li[QPB][KNN][32];
    const int tid = threadIdx.x;
    const int w = tid >> 5, lane = tid & 31;
    const int q = blockIdx.x * QPB + w;
    const float qx = xyz_last[q*3+0];
    const float qy = xyz_last[q*3+1];
    const float qz = xyz_last[q*3+2];
    const float nq = norm3_ref(qx, qy, qz);
#pragma unroll
    for (int j = 0; j < KNN; j++) { ld[w][j][lane] = FLT_MAX; li[w][j][lane] = 0x7fffffff; }

    for (int t0 = 0; t0 < N_PTS; t0 += TILE) {
        __syncthreads();
        for (int p = tid; p < TILE; p += 256) {
            float x = xyz_i[(t0+p)*3+0];
            float y = xyz_i[(t0+p)*3+1];
            float z = xyz_i[(t0+p)*3+2];
            sx[p] = x; sy[p] = y; sz[p] = z;
            sn2[p] = norm3_ref(x, y, z);
        }
        __syncthreads();
        for (int i = lane; i < TILE; i += 32) {
            float px = sx[i], py = sy[i], pz = sz[i];
            float t = __fmul_rn(qx, px);
            t = __fmaf_rn(qy, py, t);
            t = __fmaf_rn(qz, pz, t);
            float d2 = __fsub_rn(__fadd_rn(nq, sn2[i]), __fmul_rn(2.0f, t));
            if (d2 < ld[w][KNN-1][lane]) {
                int gi = t0 + i;
                int j = KNN - 1;
                while (j > 0 && ld[w][j-1][lane] > d2) {
                    ld[w][j][lane] = ld[w][j-1][lane];
                    li[w][j][lane] = li[w][j-1][lane];
                    j--;
                }
                ld[w][j][lane] = d2;
                li[w][j][lane] = gi;
            }
        }
    }
    int pos = 0;
    for (int r = 0; r < KNN; r++) {
        float v = (pos < KNN) ? ld[w][pos][lane] : FLT_MAX;
        int  gi = (pos < KNN) ? li[w][pos][lane] : 0x7fffffff;
        int  owner = lane;
#pragma unroll
        for (int off = 16; off > 0; off >>= 1) {
            float v2  = __shfl_xor_sync(0xffffffffu, v, off);
            int   g2  = __shfl_xor_sync(0xffffffffu, gi, off);
            int   o2  = __shfl_xor_sync(0xffffffffu, owner, off);
            if (v2 < v || (v2 == v && g2 < gi)) { v = v2; gi = g2; owner = o2; }
        }
        if (lane == 0) g_idx[q*KNN + r] = gi;
        if (lane == owner) pos++;
    }
}

// ---------------- pe4 moments (analytic BN stats for pe layer) ----------------
__global__ void moments_kernel(const float* __restrict__ xyz_i,
                               const float* __restrict__ xyz_last) {
    float a0=0,a1=0,a2=0,a3=0,a4=0,a5=0,a6=0,a7=0,a8=0;
    for (int s = blockIdx.x * 256 + threadIdx.x; s < NK; s += gridDim.x * 256) {
        int n = s >> 4;
        int j = g_idx[s];
        float x = xyz_i[j*3+0] - xyz_last[n*3+0];
        float y = xyz_i[j*3+1] - xyz_last[n*3+1];
        float z = xyz_i[j*3+2] - xyz_last[n*3+2];
        a0 += x; a1 += y; a2 += z;
        a3 = fmaf(x,x,a3); a4 = fmaf(y,y,a4); a5 = fmaf(z,z,a5);
        a6 = fmaf(x,y,a6); a7 = fmaf(x,z,a7); a8 = fmaf(y,z,a8);
    }
    float v[9] = {a0,a1,a2,a3,a4,a5,a6,a7,a8};
#pragma unroll
    for (int i = 0; i < 9; i++) {
#pragma unroll
        for (int off = 16; off > 0; off >>= 1)
            v[i] += __shfl_xor_sync(0xffffffffu, v[i], off);
    }
    if ((threadIdx.x & 31) == 0) {
#pragma unroll
        for (int i = 0; i < 9; i++) atomicAdd(&g_m[i], v[i]);
    }
}

__global__ void finalize_pe_kernel(const float* __restrict__ gp, const float* __restrict__ bp_,
                                   const float* __restrict__ wp1, const float* __restrict__ bp1,
                                   const float* __restrict__ t_i, const float* __restrict__ t_last) {
    int c = threadIdx.x;                 // 64
    float inv = 1.f / (float)NK;
    float mx = g_m[0]*inv, my = g_m[1]*inv, mz = g_m[2]*inv;
    float exx = g_m[3]*inv, eyy = g_m[4]*inv, ezz = g_m[5]*inv;
    float exy = g_m[6]*inv, exz = g_m[7]*inv, eyz = g_m[8]*inv;
    float w0 = wp1[c], w1 = wp1[64+c], w2 = wp1[128+c], w3 = wp1[192+c];
    float a  = bp1[c] + w3*(t_i[0] - t_last[0]);
    float lm = w0*mx + w1*my + w2*mz;
    float mean = a + lm;
    float e2 = a*a + 2.f*a*lm
             + w0*w0*exx + w1*w1*eyy + w2*w2*ezz
             + 2.f*(w0*w1*exy + w0*w2*exz + w1*w2*eyz);
    float var = e2 - mean*mean;
    float s = gp[c] * rsqrtf(var + EPS);
    g_pscale[c] = s;
    g_pshift[c] = bp_[c] - mean*s;
}

// ---------------- BN finalize (w1 / w2) ----------------
__global__ void finalize_kernel(const float* __restrict__ gamma,
                                const float* __restrict__ beta,
                                float invM, int which) {
    int c = threadIdx.x;
    const float* gs = (which == 1) ? g_s1 : g_s2;
    const float* gq = (which == 1) ? g_q1 : g_q2;
    float* sc = (which == 1) ? g_sc1 : g_sc2;
    float* sh = (which == 1) ? g_sh1 : g_sh2;
    float m = gs[c] * invM;
    float v = gq[c] * invM - m*m;
    float s = gamma[c] * rsqrtf(v + EPS);
    sc[c] = s;
    sh[c] = beta[c] - m*s;
}

// ---------------- mma.sync GEMM, 512 threads, 16 warps, 3-product bf16 split ----
// C[M,N] = f(A)[M,K] @ W[K,N] + bias
// MODE 0: plain; MODE 1: A generated from xyz (pe path), C := w1 = q - kf[idx] + pe,
//         BN1 stats; MODE 2: f = lrelu(x*sc1+sh1), C := w2, BN2 stats
template<int MODE>
__global__ __launch_bounds__(512, 1)
void mma_gemm(const float* __restrict__ A,
              const uint16_t* __restrict__ Bth, const uint16_t* __restrict__ Btl,
              const float* __restrict__ bias, float* __restrict__ C,
              int M, int N, int K,
              const float* __restrict__ xyz_i, const float* __restrict__ xyz_last,
              const float* __restrict__ t_i, const float* __restrict__ t_last,
              const float* __restrict__ wp1, const float* __restrict__ bp1) {
    __shared__ __align__(16) uint16_t Ah[128*ASTR], Al[128*ASTR];
    __shared__ __align__(16) uint16_t Bh[32*BSTR], Bl[32*BSTR];
    __shared__ float spx[128], spy[128], spz[128];
    __shared__ float swp[256], sbp[64], sps[64], ssh[64];
    __shared__ float ssc[256], ssh2[256];
    __shared__ float sbias[128], sstatS[128], sstatQ[128];

    const int tid = threadIdx.x;
    const int lane = tid & 31, wid = tid >> 5;
    const int wm = wid >> 2, wn = wid & 3;          // 4x4 warp grid, 32x32 tiles
    const int m0 = blockIdx.y * 128, n0 = blockIdx.x * 128;

    float dtv = 0.f;
    if (MODE == 1) {
        if (tid < 128) {
            int m = m0 + tid;
            int n = m >> 4;
            int j = g_idx[m];
            spx[tid] = xyz_i[j*3+0] - xyz_last[n*3+0];
            spy[tid] = xyz_i[j*3+1] - xyz_last[n*3+1];
            spz[tid] = xyz_i[j*3+2] - xyz_last[n*3+2];
        }
        if (tid < 256) swp[tid] = wp1[tid];
        if (tid < 64) { sbp[tid] = bp1[tid]; sps[tid] = g_pscale[tid]; ssh[tid] = g_pshift[tid]; }
        dtv = t_i[0] - t_last[0];
    }
    if (MODE == 2 && tid < 256) { ssc[tid] = g_sc1[tid]; ssh2[tid] = g_sh1[tid]; }
    if (tid < 128) { sbias[tid] = bias[n0 + tid]; sstatS[tid] = 0.f; sstatQ[tid] = 0.f; }
    if (MODE == 1 || MODE == 2) __syncthreads();

    float acc[2][4][4];
#pragma unroll
    for (int i = 0; i < 2; i++)
#pragma unroll
        for (int j = 0; j < 4; j++)
#pragma unroll
            for (int e = 0; e < 4; e++) acc[i][j][e] = 0.f;

    const int arow = tid >> 2, ac = (tid & 3) * 8;     // A: 128 rows x 32 k
    const int brow = tid >> 4, bc = (tid & 15) * 8;    // B: 32 k-rows x 128 n

    // prefetch stage 0
    float4 a0r, a1r;
    uint4 bhr, blr;
    if (!((MODE == 1))) {
        a0r = *(const float4*)(A + (size_t)(m0 + arow)*K + ac);
        a1r = *(const float4*)(A + (size_t)(m0 + arow)*K + ac + 4);
    }
    bhr = *(const uint4*)(Bth + (size_t)brow*N + n0 + bc);
    blr = *(const uint4*)(Btl + (size_t)brow*N + n0 + bc);

    const uint32_t AhB = su32(Ah), AlB = su32(Al), BhB = su32(Bh), BlB = su32(Bl);
    uint32_t a_off[2], b_off[2];
#pragma unroll
    for (int mt = 0; mt < 2; mt++)
        a_off[mt] = (uint32_t)(((wm*32 + mt*16 + (lane & 15))*ASTR + (lane >> 4)*8) * 2);
#pragma unroll
    for (int p = 0; p < 2; p++)
        b_off[p] = (uint32_t)(((lane & 15)*BSTR + wn*32 + p*16 + (lane >> 4)*8) * 2);

    const int nst = K >> 5;
    for (int kt = 0; kt < nst; kt++) {
        const int kb = kt * 32;
        // ---- store stage into smem ----
        if (MODE == 1) {
            float px = spx[arow], py = spy[arow], pz = spz[arow];
            float v[8];
#pragma unroll
            for (int e = 0; e < 8; e++) {
                int c = kb + ac + e;
                float hh = sbp[c];
                hh = fmaf(px,  swp[c],     hh);
                hh = fmaf(py,  swp[64+c],  hh);
                hh = fmaf(pz,  swp[128+c], hh);
                hh = fmaf(dtv, swp[192+c], hh);
                float x = fmaf(hh, sps[c], ssh[c]);
                v[e] = (x >= 0.f) ? x : SLOPE*x;
            }
            uint4 H, L;
            pack8(v, H, L);
            *(uint4*)&Ah[arow*ASTR + ac] = H;
            *(uint4*)&Al[arow*ASTR + ac] = L;
        } else {
            float v[8] = {a0r.x, a0r.y, a0r.z, a0r.w, a1r.x, a1r.y, a1r.z, a1r.w};
            if (MODE == 2) {
                int c = kb + ac;
#pragma unroll
                for (int e = 0; e < 8; e++) {
                    float x = fmaf(v[e], ssc[c+e], ssh2[c+e]);
                    v[e] = (x >= 0.f) ? x : SLOPE*x;
                }
            }
            uint4 H, L;
            pack8(v, H, L);
            *(uint4*)&Ah[arow*ASTR + ac] = H;
            *(uint4*)&Al[arow*ASTR + ac] = L;
        }
        *(uint4*)&Bh[brow*BSTR + bc] = bhr;
        *(uint4*)&Bl[brow*BSTR + bc] = blr;
        __syncthreads();

        // ---- prefetch next stage ----
        if (kt + 1 < nst) {
            const int kn = kb + 32;
            if (MODE != 1) {
                a0r = *(const float4*)(A + (size_t)(m0 + arow)*K + kn + ac);
                a1r = *(const float4*)(A + (size_t)(m0 + arow)*K + kn + ac + 4);
            }
            bhr = *(const uint4*)(Bth + (size_t)(kn + brow)*N + n0 + bc);
            blr = *(const uint4*)(Btl + (size_t)(kn + brow)*N + n0 + bc);
        }

        // ---- compute ----
#pragma unroll
        for (int ko = 0; ko < 2; ko++) {
            uint32_t ah[2][4], al_[2][4];
#pragma unroll
            for (int mt = 0; mt < 2; mt++) {
                ldsm4(ah[mt],  AhB + a_off[mt] + ko*32);
                ldsm4(al_[mt], AlB + a_off[mt] + ko*32);
            }
            uint32_t bh[4][2], bl[4][2];
#pragma unroll
            for (int p = 0; p < 2; p++) {
                uint32_t r[4];
                ldsm4t(r, BhB + b_off[p] + ko*16*BSTR*2);
                bh[2*p][0] = r[0]; bh[2*p][1] = r[1];
                bh[2*p+1][0] = r[2]; bh[2*p+1][1] = r[3];
                ldsm4t(r, BlB + b_off[p] + ko*16*BSTR*2);
                bl[2*p][0] = r[0]; bl[2*p][1] = r[1];
                bl[2*p+1][0] = r[2]; bl[2*p+1][1] = r[3];
            }
#pragma unroll
            for (int mt = 0; mt < 2; mt++)
#pragma unroll
                for (int nt = 0; nt < 4; nt++) {
                    mma16816(acc[mt][nt], ah[mt],  bh[nt]);
                    mma16816(acc[mt][nt], ah[mt],  bl[nt]);
                    mma16816(acc[mt][nt], al_[mt], bh[nt]);
                }
        }
        __syncthreads();
    }

    // ---- epilogue ----
    float colS[8], colQ[8];
#pragma unroll
    for (int i = 0; i < 8; i++) { colS[i] = 0.f; colQ[i] = 0.f; }

#pragma unroll
    for (int mt = 0; mt < 2; mt++) {
        int r0 = m0 + wm*32 + mt*16 + (lane >> 2);
        int r1 = r0 + 8;
        int j0 = 0, j1 = 0, p0 = 0, p1 = 0;
        if (MODE == 1) {
            j0 = g_idx[r0]; j1 = g_idx[r1];
            p0 = r0 >> 4;   p1 = r1 >> 4;
        }
#pragma unroll
        for (int nt = 0; nt < 4; nt++) {
            int cl = wn*32 + nt*8 + (lane & 3)*2;      // local col in [0,128)
            int c = n0 + cl;
            float v00 = acc[mt][nt][0] + sbias[cl],   v01 = acc[mt][nt][1] + sbias[cl+1];
            float v10 = acc[mt][nt][2] + sbias[cl],   v11 = acc[mt][nt][3] + sbias[cl+1];
            if (MODE == 1) {
                float2 q0 = *(const float2*)(g_q  + (size_t)p0*256 + c);
                float2 q1 = *(const float2*)(g_q  + (size_t)p1*256 + c);
                float2 k0 = *(const float2*)(g_kv + (size_t)j0*512 + c);
                float2 k1 = *(const float2*)(g_kv + (size_t)j1*512 + c);
                v00 = q0.x - k0.x + v00; v01 = q0.y - k0.y + v01;
                v10 = q1.x - k1.x + v10; v11 = q1.y - k1.y + v11;
            }
            *(float2*)(C + (size_t)r0*N + c) = make_float2(v00, v01);
            *(float2*)(C + (size_t)r1*N + c) = make_float2(v10, v11);
            if (MODE != 0) {
                colS[nt*2+0] += v00 + v10;  colS[nt*2+1] += v01 + v11;
                colQ[nt*2+0] += v00*v00 + v10*v10;
                colQ[nt*2+1] += v01*v01 + v11*v11;
            }
        }
    }
    if (MODE != 0) {
#pragma unroll
        for (int i = 0; i < 8; i++) {
#pragma unroll
            for (int off = 4; off <= 16; off <<= 1) {
                colS[i] += __shfl_xor_sync(0xffffffffu, colS[i], off);
                colQ[i] += __shfl_xor_sync(0xffffffffu, colQ[i], off);
            }
        }
        if (lane < 4) {
#pragma unroll
            for (int nt = 0; nt < 4; nt++) {
#pragma unroll
                for (int j = 0; j < 2; j++) {
                    int cl = wn*32 + nt*8 + lane*2 + j;
                    atomicAdd(&sstatS[cl], colS[nt*2+j]);
                    atomicAdd(&sstatQ[cl], colQ[nt*2+j]);
                }
            }
        }
        __syncthreads();
        if (tid < 128) {
            float* gS = (MODE == 1) ? g_s1 : g_s2;
            float* gQ = (MODE == 1) ? g_q1 : g_q2;
            atomicAdd(&gS[n0 + tid], sstatS[tid]);
            atomicAdd(&gQ[n0 + tid], sstatQ[tid]);
        }
    }
}

// ---------------- final: bn2 + lrelu + softmax(K) + weighted v-sum ----------------
// v = vf[idx] + pe, with pe reconstructed as w1 - q + kf  (exact modulo fp32 rounding)
__global__ void final_kernel(float* __restrict__ out) {
    int n = blockIdx.x, c = threadIdx.x;
    __shared__ int sidx[KNN];
    if (c < KNN) sidx[c] = g_idx[n*KNN + c];
    __syncthreads();
    float sc = g_sc2[c], sh = g_sh2[c];
    float qv = g_q[(size_t)n*COUT + c];
    float z[KNN], w1v[KNN];
    float m = -FLT_MAX;
#pragma unroll
    for (int k = 0; k < KNN; k++) {
        float x = g_w2[((size_t)n*KNN + k)*COUT + c];
        w1v[k] = g_w1[((size_t)n*KNN + k)*COUT + c];
        x = x*sc + sh;
        x = (x >= 0.f) ? x : SLOPE*x;
        z[k] = x;
        m = fmaxf(m, x);
    }
    float den = 0.f, num = 0.f;
#pragma unroll
    for (int k = 0; k < KNN; k++) {
        float e = __expf(z[k] - m);
        const float* kvrow = g_kv + (size_t)sidx[k]*512;
        float v = kvrow[256 + c] + (w1v[k] - qv + kvrow[c]);
        den += e;
        num = fmaf(e, v, num);
    }
    out[(size_t)n*COUT + c] = num / den;
}

// ---------------- launch ----------------
extern "C" void kernel_launch(void* const* d_in, const int* in_sizes, int n_in,
                              void* d_out, int out_size) {
    const float* fea_i    = (const float*)d_in[0];
    const float* fea_last = (const float*)d_in[1];
    const float* xyz_i    = (const float*)d_in[2];
    const float* xyz_last = (const float*)d_in[3];
    const float* t_i      = (const float*)d_in[4];
    const float* t_last   = (const float*)d_in[5];
    const float* wp1 = (const float*)d_in[6];
    const float* bp1 = (const float*)d_in[7];
    const float* gp  = (const float*)d_in[8];
    const float* bp  = (const float*)d_in[9];
    const float* wp2 = (const float*)d_in[10];
    const float* bp2 = (const float*)d_in[11];
    const float* wq  = (const float*)d_in[12];
    const float* bq  = (const float*)d_in[13];
    const float* wk  = (const float*)d_in[14];
    const float* bk  = (const float*)d_in[15];
    const float* wv  = (const float*)d_in[16];
    const float* bv  = (const float*)d_in[17];
    const float* gw1 = (const float*)d_in[18];
    const float* bw1 = (const float*)d_in[19];
    const float* ww  = (const float*)d_in[20];
    const float* bw  = (const float*)d_in[21];
    const float* gw2 = (const float*)d_in[22];
    const float* bw2 = (const float*)d_in[23];
    float* out = (float*)d_out;

    void* p;
    cudaGetSymbolAddress(&p, g_q);   float* p_q   = (float*)p;
    cudaGetSymbolAddress(&p, g_kv);  float* p_kv  = (float*)p;
    cudaGetSymbolAddress(&p, g_bkv); float* p_bkv = (float*)p;
    cudaGetSymbolAddress(&p, g_bth); uint16_t* p_bth = (uint16_t*)p;
    cudaGetSymbolAddress(&p, g_btl); uint16_t* p_btl = (uint16_t*)p;
    cudaGetSymbolAddress(&p, g_w1);  float* p_w1  = (float*)p;
    cudaGetSymbolAddress(&p, g_w2);  float* p_w2  = (float*)p;

    zero_stats_kernel<<<1, 256>>>();
    bias_kv_kernel<<<2, 256>>>(bk, bv);
    split_w_kernel<<<(TOTW + 255)/256, 256>>>(wq, wk, wv, wp2, ww);

    // 1) kNN
    knn_kernel<<<N_PTS/QPB, 256>>>(xyz_i, xyz_last);

    // 2) projections
    mma_gemm<0><<<dim3(2, 64), 512>>>(fea_last, p_bth + OQ,  p_btl + OQ,  bq,    p_q,  N_PTS, 256, CIN,
                                      nullptr, nullptr, nullptr, nullptr, nullptr, nullptr);
    mma_gemm<0><<<dim3(4, 64), 512>>>(fea_i,    p_bth + OKV, p_btl + OKV, p_bkv, p_kv, N_PTS, 512, CIN,
                                      nullptr, nullptr, nullptr, nullptr, nullptr, nullptr);

    // 3) analytic pe-BN stats
    moments_kernel<<<64, 256>>>(xyz_i, xyz_last);
    finalize_pe_kernel<<<1, HDIM>>>(gp, bp, wp1, bp1, t_i, t_last);

    // 4) pe GEMM (A generated) -> w1 = q - kf + pe directly, + BN1 stats
    mma_gemm<1><<<dim3(2, 1024), 512>>>(nullptr, p_bth + OP2, p_btl + OP2, bp2, p_w1, NK, 256, HDIM,
                                        xyz_i, xyz_last, t_i, t_last, wp1, bp1);
    finalize_kernel<<<1, COUT>>>(gw1, bw1, 1.f/(float)NK, 1);

    // 5) w2 GEMM + BN2 stats
    mma_gemm<2><<<dim3(2, 1024), 512>>>(p_w1, p_bth + OW, p_btl + OW, bw, p_w2, NK, 256, CIN,
                                        nullptr, nullptr, nullptr, nullptr, nullptr, nullptr);
    finalize_kernel<<<1, COUT>>>(gw2, bw2, 1.f/(float)NK, 2);

    // 6) softmax over K + weighted v-sum (pe reconstructed from w1)
    final_kernel<<<N_PTS, COUT>>>(out);
}

// round 7
// speedup vs baseline: 2.2642x; 1.2416x over previous
#include <cuda_runtime.h>
#include <cuda_bf16.h>
#include <cstdint>
#include <cfloat>

#define N_PTS 8192
#define KNN   16
#define CIN   256
#define COUT  256
#define NK    (N_PTS*KNN)       // 131072
#define HDIM  64
#define SLOPE 0.01f
#define EPS   1e-5f
#define TILE  1024
#define QPB   8
#define ASTR  40                // A smem row stride in halves
#define BSTR  136               // B smem row stride in halves

// weight-split buffer offsets (natural [K,N] layout, bf16 hi/lo)
#define OQ   0
#define OKV  65536              // 256*256
#define OP2  196608             // + 256*512
#define OW   212992             // + 64*256
#define TOTW 278528             // + 256*256

// ---------------- device scratch (static, allocation-free) ----------------
__device__ int      g_idx[NK];
__device__ float    g_q  [N_PTS*COUT];
__device__ float    g_kv [N_PTS*512];     // [kf | vf]
__device__ float    g_bkv[512];
__device__ uint16_t g_bth[TOTW];          // weights bf16 hi, [K,N]
__device__ uint16_t g_btl[TOTW];          // weights bf16 lo, [K,N]
__device__ float    g_w1 [NK*COUT];
__device__ float    g_w2 [NK*COUT];
__device__ float    g_m[9];               // pe4 moments
__device__ float    g_pscale[HDIM], g_pshift[HDIM];
__device__ float    g_s1[COUT], g_q1[COUT], g_sc1[COUT], g_sh1[COUT];
__device__ float    g_s2[COUT], g_q2[COUT], g_sc2[COUT], g_sh2[COUT];

// ---------------- PTX helpers ----------------
__device__ __forceinline__ uint32_t su32(const void* p) {
    return (uint32_t)__cvta_generic_to_shared(p);
}
__device__ __forceinline__ void ldsm4(uint32_t r[4], uint32_t a) {
    asm volatile("ldmatrix.sync.aligned.m8n8.x4.shared.b16 {%0,%1,%2,%3}, [%4];"
        : "=r"(r[0]), "=r"(r[1]), "=r"(r[2]), "=r"(r[3]) : "r"(a));
}
__device__ __forceinline__ void ldsm4t(uint32_t r[4], uint32_t a) {
    asm volatile("ldmatrix.sync.aligned.m8n8.x4.trans.shared.b16 {%0,%1,%2,%3}, [%4];"
        : "=r"(r[0]), "=r"(r[1]), "=r"(r[2]), "=r"(r[3]) : "r"(a));
}
__device__ __forceinline__ void mma16816(float c[4], const uint32_t a[4], const uint32_t b[2]) {
    asm volatile("mma.sync.aligned.m16n8k16.row.col.f32.bf16.bf16.f32 "
        "{%0,%1,%2,%3}, {%4,%5,%6,%7}, {%8,%9}, {%0,%1,%2,%3};"
        : "+f"(c[0]), "+f"(c[1]), "+f"(c[2]), "+f"(c[3])
        : "r"(a[0]), "r"(a[1]), "r"(a[2]), "r"(a[3]), "r"(b[0]), "r"(b[1]));
}
__device__ __forceinline__ void split1(float x, uint16_t& hi, uint16_t& lo) {
    __nv_bfloat16 h = __float2bfloat16_rn(x);
    __nv_bfloat16 l = __float2bfloat16_rn(x - __bfloat162float(h));
    hi = *(uint16_t*)&h; lo = *(uint16_t*)&l;
}
__device__ __forceinline__ void pack8(const float* v, uint4& H, uint4& L) {
    uint16_t h[8], l[8];
#pragma unroll
    for (int i = 0; i < 8; i++) split1(v[i], h[i], l[i]);
    H.x = (uint32_t)h[0] | ((uint32_t)h[1] << 16);
    H.y = (uint32_t)h[2] | ((uint32_t)h[3] << 16);
    H.z = (uint32_t)h[4] | ((uint32_t)h[5] << 16);
    H.w = (uint32_t)h[6] | ((uint32_t)h[7] << 16);
    L.x = (uint32_t)l[0] | ((uint32_t)l[1] << 16);
    L.y = (uint32_t)l[2] | ((uint32_t)l[3] << 16);
    L.z = (uint32_t)l[4] | ((uint32_t)l[5] << 16);
    L.w = (uint32_t)l[6] | ((uint32_t)l[7] << 16);
}

// ---------------- zero stats ----------------
__global__ void zero_stats_kernel() {
    int t = threadIdx.x;
    if (t < 9) g_m[t] = 0.f;
    if (t < COUT) { g_s1[t] = 0.f; g_q1[t] = 0.f; g_s2[t] = 0.f; g_q2[t] = 0.f; }
}

// ---------------- bias concat + weight split (bf16 hi/lo, [K,N]) ----------
__global__ void bias_kv_kernel(const float* __restrict__ bk, const float* __restrict__ bv) {
    int i = blockIdx.x * 256 + threadIdx.x;
    if (i < 512) g_bkv[i] = (i < 256) ? bk[i] : bv[i - 256];
}

__global__ void split_w_kernel(const float* __restrict__ wq,
                               const float* __restrict__ wk, const float* __restrict__ wv,
                               const float* __restrict__ wp2, const float* __restrict__ ww) {
    int i = blockIdx.x * 256 + threadIdx.x;
    if (i >= TOTW) return;
    float val;
    if (i < OKV) {                       // wq [256,256]
        val = wq[i];
    } else if (i < OP2) {                // wkv [256,512]: row k = [wk_k | wv_k]
        int j = i - OKV, k = j >> 9, n = j & 511;
        val = (n < 256) ? wk[k*256 + n] : wv[k*256 + (n - 256)];
    } else if (i < OW) {                 // wp2 [64,256]
        val = wp2[i - OP2];
    } else {                             // ww [256,256]
        val = ww[i - OW];
    }
    uint16_t h, l;
    split1(val, h, l);
    g_bth[i] = h; g_btl[i] = l;
}

// ---------------- kNN: float4 tiles + register top-16 ----------------
// d2 formula bit-identical to the passing version (all _rn intrinsics).
__device__ __forceinline__ float norm3_ref(float x, float y, float z) {
    return __fadd_rn(__fadd_rn(__fmul_rn(x, x), __fmul_rn(y, y)), __fmul_rn(z, z));
}

__global__ void knn_kernel(const float* __restrict__ xyz_i,
                           const float* __restrict__ xyz_last) {
    __shared__ float4 sp[TILE];
    __shared__ float ld[QPB][KNN][32];
    __shared__ int   li[QPB][KNN][32];
    const int tid = threadIdx.x;
    const int w = tid >> 5, lane = tid & 31;
    const int q = blockIdx.x * QPB + w;
    const float qx = xyz_last[q*3+0];
    const float qy = xyz_last[q*3+1];
    const float qz = xyz_last[q*3+2];
    const float nq = norm3_ref(qx, qy, qz);

    float dist[KNN];
    int   idx [KNN];
#pragma unroll
    for (int j = 0; j < KNN; j++) { dist[j] = FLT_MAX; idx[j] = 0x7fffffff; }

    for (int t0 = 0; t0 < N_PTS; t0 += TILE) {
        __syncthreads();
        for (int p = tid; p < TILE; p += 256) {
            float x = xyz_i[(t0+p)*3+0];
            float y = xyz_i[(t0+p)*3+1];
            float z = xyz_i[(t0+p)*3+2];
            sp[p] = make_float4(x, y, z, norm3_ref(x, y, z));
        }
        __syncthreads();
        for (int i = lane; i < TILE; i += 32) {
            float4 pv = sp[i];
            float t = __fmul_rn(qx, pv.x);
            t = __fmaf_rn(qy, pv.y, t);
            t = __fmaf_rn(qz, pv.z, t);
            float d2 = __fsub_rn(__fadd_rn(nq, pv.w), __fmul_rn(2.0f, t));
            if (d2 < dist[KNN-1]) {
                dist[KNN-1] = d2;
                idx[KNN-1]  = t0 + i;
                // bubble the new element to its sorted position (predicated, registers)
#pragma unroll
                for (int j = KNN-1; j > 0; j--) {
                    float da = dist[j-1], db = dist[j];
                    int   ia = idx[j-1],  ib = idx[j];
                    bool sw = db < da;   // strict: equal keeps earlier (lower idx) first
                    dist[j-1] = sw ? db : da;
                    dist[j]   = sw ? da : db;
                    idx[j-1]  = sw ? ib : ia;
                    idx[j]    = sw ? ia : ib;
                }
            }
        }
    }
    // dump registers to shared, then cross-lane merge (unchanged semantics)
#pragma unroll
    for (int j = 0; j < KNN; j++) { ld[w][j][lane] = dist[j]; li[w][j][lane] = idx[j]; }
    __syncwarp();

    int pos = 0;
    for (int r = 0; r < KNN; r++) {
        float v = (pos < KNN) ? ld[w][pos][lane] : FLT_MAX;
        int  gi = (pos < KNN) ? li[w][pos][lane] : 0x7fffffff;
        int  owner = lane;
#pragma unroll
        for (int off = 16; off > 0; off >>= 1) {
            float v2  = __shfl_xor_sync(0xffffffffu, v, off);
            int   g2  = __shfl_xor_sync(0xffffffffu, gi, off);
            int   o2  = __shfl_xor_sync(0xffffffffu, owner, off);
            if (v2 < v || (v2 == v && g2 < gi)) { v = v2; gi = g2; owner = o2; }
        }
        if (lane == 0) g_idx[q*KNN + r] = gi;
        if (lane == owner) pos++;
    }
}

// ---------------- pe4 moments (analytic BN stats for pe layer) ----------------
__global__ void moments_kernel(const float* __restrict__ xyz_i,
                               const float* __restrict__ xyz_last) {
    float a0=0,a1=0,a2=0,a3=0,a4=0,a5=0,a6=0,a7=0,a8=0;
    for (int s = blockIdx.x * 256 + threadIdx.x; s < NK; s += gridDim.x * 256) {
        int n = s >> 4;
        int j = g_idx[s];
        float x = xyz_i[j*3+0] - xyz_last[n*3+0];
        float y = xyz_i[j*3+1] - xyz_last[n*3+1];
        float z = xyz_i[j*3+2] - xyz_last[n*3+2];
        a0 += x; a1 += y; a2 += z;
        a3 = fmaf(x,x,a3); a4 = fmaf(y,y,a4); a5 = fmaf(z,z,a5);
        a6 = fmaf(x,y,a6); a7 = fmaf(x,z,a7); a8 = fmaf(y,z,a8);
    }
    float v[9] = {a0,a1,a2,a3,a4,a5,a6,a7,a8};
#pragma unroll
    for (int i = 0; i < 9; i++) {
#pragma unroll
        for (int off = 16; off > 0; off >>= 1)
            v[i] += __shfl_xor_sync(0xffffffffu, v[i], off);
    }
    if ((threadIdx.x & 31) == 0) {
#pragma unroll
        for (int i = 0; i < 9; i++) atomicAdd(&g_m[i], v[i]);
    }
}

__global__ void finalize_pe_kernel(const float* __restrict__ gp, const float* __restrict__ bp_,
                                   const float* __restrict__ wp1, const float* __restrict__ bp1,
                                   const float* __restrict__ t_i, const float* __restrict__ t_last) {
    int c = threadIdx.x;                 // 64
    float inv = 1.f / (float)NK;
    float mx = g_m[0]*inv, my = g_m[1]*inv, mz = g_m[2]*inv;
    float exx = g_m[3]*inv, eyy = g_m[4]*inv, ezz = g_m[5]*inv;
    float exy = g_m[6]*inv, exz = g_m[7]*inv, eyz = g_m[8]*inv;
    float w0 = wp1[c], w1 = wp1[64+c], w2 = wp1[128+c], w3 = wp1[192+c];
    float a  = bp1[c] + w3*(t_i[0] - t_last[0]);
    float lm = w0*mx + w1*my + w2*mz;
    float mean = a + lm;
    float e2 = a*a + 2.f*a*lm
             + w0*w0*exx + w1*w1*eyy + w2*w2*ezz
             + 2.f*(w0*w1*exy + w0*w2*exz + w1*w2*eyz);
    float var = e2 - mean*mean;
    float s = gp[c] * rsqrtf(var + EPS);
    g_pscale[c] = s;
    g_pshift[c] = bp_[c] - mean*s;
}

// ---------------- BN finalize (w1 / w2) ----------------
__global__ void finalize_kernel(const float* __restrict__ gamma,
                                const float* __restrict__ beta,
                                float invM, int which) {
    int c = threadIdx.x;
    const float* gs = (which == 1) ? g_s1 : g_s2;
    const float* gq = (which == 1) ? g_q1 : g_q2;
    float* sc = (which == 1) ? g_sc1 : g_sc2;
    float* sh = (which == 1) ? g_sh1 : g_sh2;
    float m = gs[c] * invM;
    float v = gq[c] * invM - m*m;
    float s = gamma[c] * rsqrtf(v + EPS);
    sc[c] = s;
    sh[c] = beta[c] - m*s;
}

// ---------------- mma.sync GEMM, 512 threads, 16 warps, 3-product bf16 split ----
// C[M,N] = f(A)[M,K] @ W[K,N] + bias
// MODE 0: plain; MODE 1: A generated from xyz (pe path), C := w1 = q - kf[idx] + pe,
//         BN1 stats; MODE 2: f = lrelu(x*sc1+sh1), C := w2, BN2 stats
template<int MODE>
__global__ __launch_bounds__(512, 1)
void mma_gemm(const float* __restrict__ A,
              const uint16_t* __restrict__ Bth, const uint16_t* __restrict__ Btl,
              const float* __restrict__ bias, float* __restrict__ C,
              int M, int N, int K,
              const float* __restrict__ xyz_i, const float* __restrict__ xyz_last,
              const float* __restrict__ t_i, const float* __restrict__ t_last,
              const float* __restrict__ wp1, const float* __restrict__ bp1) {
    __shared__ __align__(16) uint16_t Ah[128*ASTR], Al[128*ASTR];
    __shared__ __align__(16) uint16_t Bh[32*BSTR], Bl[32*BSTR];
    __shared__ float spx[128], spy[128], spz[128];
    __shared__ float swp[256], sbp[64], sps[64], ssh[64];
    __shared__ float ssc[256], ssh2[256];
    __shared__ float sbias[128], sstatS[128], sstatQ[128];

    const int tid = threadIdx.x;
    const int lane = tid & 31, wid = tid >> 5;
    const int wm = wid >> 2, wn = wid & 3;          // 4x4 warp grid, 32x32 tiles
    const int m0 = blockIdx.y * 128, n0 = blockIdx.x * 128;

    float dtv = 0.f;
    if (MODE == 1) {
        if (tid < 128) {
            int m = m0 + tid;
            int n = m >> 4;
            int j = g_idx[m];
            spx[tid] = xyz_i[j*3+0] - xyz_last[n*3+0];
            spy[tid] = xyz_i[j*3+1] - xyz_last[n*3+1];
            spz[tid] = xyz_i[j*3+2] - xyz_last[n*3+2];
        }
        if (tid < 256) swp[tid] = wp1[tid];
        if (tid < 64) { sbp[tid] = bp1[tid]; sps[tid] = g_pscale[tid]; ssh[tid] = g_pshift[tid]; }
        dtv = t_i[0] - t_last[0];
    }
    if (MODE == 2 && tid < 256) { ssc[tid] = g_sc1[tid]; ssh2[tid] = g_sh1[tid]; }
    if (tid < 128) { sbias[tid] = bias[n0 + tid]; sstatS[tid] = 0.f; sstatQ[tid] = 0.f; }
    if (MODE == 1 || MODE == 2) __syncthreads();

    float acc[2][4][4];
#pragma unroll
    for (int i = 0; i < 2; i++)
#pragma unroll
        for (int j = 0; j < 4; j++)
#pragma unroll
            for (int e = 0; e < 4; e++) acc[i][j][e] = 0.f;

    const int arow = tid >> 2, ac = (tid & 3) * 8;     // A: 128 rows x 32 k
    const int brow = tid >> 4, bc = (tid & 15) * 8;    // B: 32 k-rows x 128 n

    // prefetch stage 0
    float4 a0r, a1r;
    uint4 bhr, blr;
    if (!((MODE == 1))) {
        a0r = *(const float4*)(A + (size_t)(m0 + arow)*K + ac);
        a1r = *(const float4*)(A + (size_t)(m0 + arow)*K + ac + 4);
    }
    bhr = *(const uint4*)(Bth + (size_t)brow*N + n0 + bc);
    blr = *(const uint4*)(Btl + (size_t)brow*N + n0 + bc);

    const uint32_t AhB = su32(Ah), AlB = su32(Al), BhB = su32(Bh), BlB = su32(Bl);
    uint32_t a_off[2], b_off[2];
#pragma unroll
    for (int mt = 0; mt < 2; mt++)
        a_off[mt] = (uint32_t)(((wm*32 + mt*16 + (lane & 15))*ASTR + (lane >> 4)*8) * 2);
#pragma unroll
    for (int p = 0; p < 2; p++)
        b_off[p] = (uint32_t)(((lane & 15)*BSTR + wn*32 + p*16 + (lane >> 4)*8) * 2);

    const int nst = K >> 5;
    for (int kt = 0; kt < nst; kt++) {
        const int kb = kt * 32;
        // ---- store stage into smem ----
        if (MODE == 1) {
            float px = spx[arow], py = spy[arow], pz = spz[arow];
            float v[8];
#pragma unroll
            for (int e = 0; e < 8; e++) {
                int c = kb + ac + e;
                float hh = sbp[c];
                hh = fmaf(px,  swp[c],     hh);
                hh = fmaf(py,  swp[64+c],  hh);
                hh = fmaf(pz,  swp[128+c], hh);
                hh = fmaf(dtv, swp[192+c], hh);
                float x = fmaf(hh, sps[c], ssh[c]);
                v[e] = (x >= 0.f) ? x : SLOPE*x;
            }
            uint4 H, L;
            pack8(v, H, L);
            *(uint4*)&Ah[arow*ASTR + ac] = H;
            *(uint4*)&Al[arow*ASTR + ac] = L;
        } else {
            float v[8] = {a0r.x, a0r.y, a0r.z, a0r.w, a1r.x, a1r.y, a1r.z, a1r.w};
            if (MODE == 2) {
                int c = kb + ac;
#pragma unroll
                for (int e = 0; e < 8; e++) {
                    float x = fmaf(v[e], ssc[c+e], ssh2[c+e]);
                    v[e] = (x >= 0.f) ? x : SLOPE*x;
                }
            }
            uint4 H, L;
            pack8(v, H, L);
            *(uint4*)&Ah[arow*ASTR + ac] = H;
            *(uint4*)&Al[arow*ASTR + ac] = L;
        }
        *(uint4*)&Bh[brow*BSTR + bc] = bhr;
        *(uint4*)&Bl[brow*BSTR + bc] = blr;
        __syncthreads();

        // ---- prefetch next stage ----
        if (kt + 1 < nst) {
            const int kn = kb + 32;
            if (MODE != 1) {
                a0r = *(const float4*)(A + (size_t)(m0 + arow)*K + kn + ac);
                a1r = *(const float4*)(A + (size_t)(m0 + arow)*K + kn + ac + 4);
            }
            bhr = *(const uint4*)(Bth + (size_t)(kn + brow)*N + n0 + bc);
            blr = *(const uint4*)(Btl + (size_t)(kn + brow)*N + n0 + bc);
        }

        // ---- compute ----
#pragma unroll
        for (int ko = 0; ko < 2; ko++) {
            uint32_t ah[2][4], al_[2][4];
#pragma unroll
            for (int mt = 0; mt < 2; mt++) {
                ldsm4(ah[mt],  AhB + a_off[mt] + ko*32);
                ldsm4(al_[mt], AlB + a_off[mt] + ko*32);
            }
            uint32_t bh[4][2], bl[4][2];
#pragma unroll
            for (int p = 0; p < 2; p++) {
                uint32_t r[4];
                ldsm4t(r, BhB + b_off[p] + ko*16*BSTR*2);
                bh[2*p][0] = r[0]; bh[2*p][1] = r[1];
                bh[2*p+1][0] = r[2]; bh[2*p+1][1] = r[3];
                ldsm4t(r, BlB + b_off[p] + ko*16*BSTR*2);
                bl[2*p][0] = r[0]; bl[2*p][1] = r[1];
                bl[2*p+1][0] = r[2]; bl[2*p+1][1] = r[3];
            }
#pragma unroll
            for (int mt = 0; mt < 2; mt++)
#pragma unroll
                for (int nt = 0; nt < 4; nt++) {
                    mma16816(acc[mt][nt], ah[mt],  bh[nt]);
                    mma16816(acc[mt][nt], ah[mt],  bl[nt]);
                    mma16816(acc[mt][nt], al_[mt], bh[nt]);
                }
        }
        __syncthreads();
    }

    // ---- epilogue ----
    float colS[8], colQ[8];
#pragma unroll
    for (int i = 0; i < 8; i++) { colS[i] = 0.f; colQ[i] = 0.f; }

#pragma unroll
    for (int mt = 0; mt < 2; mt++) {
        int r0 = m0 + wm*32 + mt*16 + (lane >> 2);
        int r1 = r0 + 8;
        int j0 = 0, j1 = 0, p0 = 0, p1 = 0;
        if (MODE == 1) {
            j0 = g_idx[r0]; j1 = g_idx[r1];
            p0 = r0 >> 4;   p1 = r1 >> 4;
        }
#pragma unroll
        for (int nt = 0; nt < 4; nt++) {
            int cl = wn*32 + nt*8 + (lane & 3)*2;      // local col in [0,128)
            int c = n0 + cl;
            float v00 = acc[mt][nt][0] + sbias[cl],   v01 = acc[mt][nt][1] + sbias[cl+1];
            float v10 = acc[mt][nt][2] + sbias[cl],   v11 = acc[mt][nt][3] + sbias[cl+1];
            if (MODE == 1) {
                float2 q0 = *(const float2*)(g_q  + (size_t)p0*256 + c);
                float2 q1 = *(const float2*)(g_q  + (size_t)p1*256 + c);
                float2 k0 = *(const float2*)(g_kv + (size_t)j0*512 + c);
                float2 k1 = *(const float2*)(g_kv + (size_t)j1*512 + c);
                v00 = q0.x - k0.x + v00; v01 = q0.y - k0.y + v01;
                v10 = q1.x - k1.x + v10; v11 = q1.y - k1.y + v11;
            }
            *(float2*)(C + (size_t)r0*N + c) = make_float2(v00, v01);
            *(float2*)(C + (size_t)r1*N + c) = make_float2(v10, v11);
            if (MODE != 0) {
                colS[nt*2+0] += v00 + v10;  colS[nt*2+1] += v01 + v11;
                colQ[nt*2+0] += v00*v00 + v10*v10;
                colQ[nt*2+1] += v01*v01 + v11*v11;
            }
        }
    }
    if (MODE != 0) {
#pragma unroll
        for (int i = 0; i < 8; i++) {
#pragma unroll
            for (int off = 4; off <= 16; off <<= 1) {
                colS[i] += __shfl_xor_sync(0xffffffffu, colS[i], off);
                colQ[i] += __shfl_xor_sync(0xffffffffu, colQ[i], off);
            }
        }
        if (lane < 4) {
#pragma unroll
            for (int nt = 0; nt < 4; nt++) {
#pragma unroll
                for (int j = 0; j < 2; j++) {
                    int cl = wn*32 + nt*8 + lane*2 + j;
                    atomicAdd(&sstatS[cl], colS[nt*2+j]);
                    atomicAdd(&sstatQ[cl], colQ[nt*2+j]);
                }
            }
        }
        __syncthreads();
        if (tid < 128) {
            float* gS = (MODE == 1) ? g_s1 : g_s2;
            float* gQ = (MODE == 1) ? g_q1 : g_q2;
            atomicAdd(&gS[n0 + tid], sstatS[tid]);
            atomicAdd(&gQ[n0 + tid], sstatQ[tid]);
        }
    }
}

// ---------------- final: bn2 + lrelu + softmax(K) + weighted v-sum ----------------
// v = vf[idx] + pe, with pe reconstructed as w1 - q + kf  (exact modulo fp32 rounding)
__global__ void final_kernel(float* __restrict__ out) {
    int n = blockIdx.x, c = threadIdx.x;
    __shared__ int sidx[KNN];
    if (c < KNN) sidx[c] = g_idx[n*KNN + c];
    __syncthreads();
    float sc = g_sc2[c], sh = g_sh2[c];
    float qv = g_q[(size_t)n*COUT + c];
    float z[KNN], w1v[KNN];
    float m = -FLT_MAX;
#pragma unroll
    for (int k = 0; k < KNN; k++) {
        float x = g_w2[((size_t)n*KNN + k)*COUT + c];
        w1v[k] = g_w1[((size_t)n*KNN + k)*COUT + c];
        x = x*sc + sh;
        x = (x >= 0.f) ? x : SLOPE*x;
        z[k] = x;
        m = fmaxf(m, x);
    }
    float den = 0.f, num = 0.f;
#pragma unroll
    for (int k = 0; k < KNN; k++) {
        float e = __expf(z[k] - m);
        const float* kvrow = g_kv + (size_t)sidx[k]*512;
        float v = kvrow[256 + c] + (w1v[k] - qv + kvrow[c]);
        den += e;
        num = fmaf(e, v, num);
    }
    out[(size_t)n*COUT + c] = num / den;
}

// ---------------- launch ----------------
extern "C" void kernel_launch(void* const* d_in, const int* in_sizes, int n_in,
                              void* d_out, int out_size) {
    const float* fea_i    = (const float*)d_in[0];
    const float* fea_last = (const float*)d_in[1];
    const float* xyz_i    = (const float*)d_in[2];
    const float* xyz_last = (const float*)d_in[3];
    const float* t_i      = (const float*)d_in[4];
    const float* t_last   = (const float*)d_in[5];
    const float* wp1 = (const float*)d_in[6];
    const float* bp1 = (const float*)d_in[7];
    const float* gp  = (const float*)d_in[8];
    const float* bp  = (const float*)d_in[9];
    const float* wp2 = (const float*)d_in[10];
    const float* bp2 = (const float*)d_in[11];
    const float* wq  = (const float*)d_in[12];
    const float* bq  = (const float*)d_in[13];
    const float* wk  = (const float*)d_in[14];
    const float* bk  = (const float*)d_in[15];
    const float* wv  = (const float*)d_in[16];
    const float* bv  = (const float*)d_in[17];
    const float* gw1 = (const float*)d_in[18];
    const float* bw1 = (const float*)d_in[19];
    const float* ww  = (const float*)d_in[20];
    const float* bw  = (const float*)d_in[21];
    const float* gw2 = (const float*)d_in[22];
    const float* bw2 = (const float*)d_in[23];
    float* out = (float*)d_out;

    void* p;
    cudaGetSymbolAddress(&p, g_q);   float* p_q   = (float*)p;
    cudaGetSymbolAddress(&p, g_kv);  float* p_kv  = (float*)p;
    cudaGetSymbolAddress(&p, g_bkv); float* p_bkv = (float*)p;
    cudaGetSymbolAddress(&p, g_bth); uint16_t* p_bth = (uint16_t*)p;
    cudaGetSymbolAddress(&p, g_btl); uint16_t* p_btl = (uint16_t*)p;
    cudaGetSymbolAddress(&p, g_w1);  float* p_w1  = (float*)p;
    cudaGetSymbolAddress(&p, g_w2);  float* p_w2  = (float*)p;

    zero_stats_kernel<<<1, 256>>>();
    bias_kv_kernel<<<2, 256>>>(bk, bv);
    split_w_kernel<<<(TOTW + 255)/256, 256>>>(wq, wk, wv, wp2, ww);

    // 1) kNN
    knn_kernel<<<N_PTS/QPB, 256>>>(xyz_i, xyz_last);

    // 2) projections
    mma_gemm<0><<<dim3(2, 64), 512>>>(fea_last, p_bth + OQ,  p_btl + OQ,  bq,    p_q,  N_PTS, 256, CIN,
                                      nullptr, nullptr, nullptr, nullptr, nullptr, nullptr);
    mma_gemm<0><<<dim3(4, 64), 512>>>(fea_i,    p_bth + OKV, p_btl + OKV, p_bkv, p_kv, N_PTS, 512, CIN,
                                      nullptr, nullptr, nullptr, nullptr, nullptr, nullptr);

    // 3) analytic pe-BN stats
    moments_kernel<<<64, 256>>>(xyz_i, xyz_last);
    finalize_pe_kernel<<<1, HDIM>>>(gp, bp, wp1, bp1, t_i, t_last);

    // 4) pe GEMM (A generated) -> w1 = q - kf + pe directly, + BN1 stats
    mma_gemm<1><<<dim3(2, 1024), 512>>>(nullptr, p_bth + OP2, p_btl + OP2, bp2, p_w1, NK, 256, HDIM,
                                        xyz_i, xyz_last, t_i, t_last, wp1, bp1);
    finalize_kernel<<<1, COUT>>>(gw1, bw1, 1.f/(float)NK, 1);

    // 5) w2 GEMM + BN2 stats
    mma_gemm<2><<<dim3(2, 1024), 512>>>(p_w1, p_bth + OW, p_btl + OW, bw, p_w2, NK, 256, CIN,
                                        nullptr, nullptr, nullptr, nullptr, nullptr, nullptr);
    finalize_kernel<<<1, COUT>>>(gw2, bw2, 1.f/(float)NK, 2);

    // 6) softmax over K + weighted v-sum (pe reconstructed from w1)
    final_kernel<<<N_PTS, COUT>>>(out);
}

// round 8
// speedup vs baseline: 2.9760x; 1.3144x over previous
#include <cuda_runtime.h>
#include <cuda_bf16.h>
#include <cstdint>
#include <cfloat>

#define N_PTS 8192
#define KNN   16
#define CIN   256
#define COUT  256
#define NK    (N_PTS*KNN)       // 131072
#define HDIM  64
#define SLOPE 0.01f
#define EPS   1e-5f
#define TILE  1024
#define QPB   8
#define ASTR  40                // A smem row stride in halves
#define BSTR  136               // B smem row stride in halves

// kNN grid params
#define GDIM  8
#define GCELLS (GDIM*GDIM*GDIM)   // 512
#define KRAD  0.25f
#define KRAD2 0.0625f

// weight-split buffer offsets (natural [K,N] layout, bf16 hi/lo)
#define OQ   0
#define OKV  65536              // 256*256
#define OP2  196608             // + 256*512
#define OW   212992             // + 64*256
#define TOTW 278528             // + 256*256

// ---------------- device scratch (static, allocation-free) ----------------
__device__ int      g_idx[NK];
__device__ float    g_q  [N_PTS*COUT];
__device__ float    g_kv [N_PTS*512];     // [kf | vf]
__device__ float    g_bkv[512];
__device__ uint16_t g_bth[TOTW];          // weights bf16 hi, [K,N]
__device__ uint16_t g_btl[TOTW];          // weights bf16 lo, [K,N]
__device__ float    g_w1 [NK*COUT];
__device__ float    g_w2 [NK*COUT];
__device__ float    g_m[9];               // pe4 moments
__device__ float    g_pscale[HDIM], g_pshift[HDIM];
__device__ float    g_s1[COUT], g_q1[COUT], g_sc1[COUT], g_sh1[COUT];
__device__ float    g_s2[COUT], g_q2[COUT], g_sc2[COUT], g_sh2[COUT];
// grid structures
__device__ int      g_cellCnt[GCELLS];
__device__ int      g_cellFill[GCELLS];
__device__ int      g_cellStart[GCELLS+1];
__device__ float4   g_spts[N_PTS];
__device__ int      g_sidx[N_PTS];
__device__ int      g_fb[N_PTS];

// ---------------- PTX helpers ----------------
__device__ __forceinline__ uint32_t su32(const void* p) {
    return (uint32_t)__cvta_generic_to_shared(p);
}
__device__ __forceinline__ void ldsm4(uint32_t r[4], uint32_t a) {
    asm volatile("ldmatrix.sync.aligned.m8n8.x4.shared.b16 {%0,%1,%2,%3}, [%4];"
        : "=r"(r[0]), "=r"(r[1]), "=r"(r[2]), "=r"(r[3]) : "r"(a));
}
__device__ __forceinline__ void ldsm4t(uint32_t r[4], uint32_t a) {
    asm volatile("ldmatrix.sync.aligned.m8n8.x4.trans.shared.b16 {%0,%1,%2,%3}, [%4];"
        : "=r"(r[0]), "=r"(r[1]), "=r"(r[2]), "=r"(r[3]) : "r"(a));
}
__device__ __forceinline__ void mma16816(float c[4], const uint32_t a[4], const uint32_t b[2]) {
    asm volatile("mma.sync.aligned.m16n8k16.row.col.f32.bf16.bf16.f32 "
        "{%0,%1,%2,%3}, {%4,%5,%6,%7}, {%8,%9}, {%0,%1,%2,%3};"
        : "+f"(c[0]), "+f"(c[1]), "+f"(c[2]), "+f"(c[3])
        : "r"(a[0]), "r"(a[1]), "r"(a[2]), "r"(a[3]), "r"(b[0]), "r"(b[1]));
}
__device__ __forceinline__ void split1(float x, uint16_t& hi, uint16_t& lo) {
    __nv_bfloat16 h = __float2bfloat16_rn(x);
    __nv_bfloat16 l = __float2bfloat16_rn(x - __bfloat162float(h));
    hi = *(uint16_t*)&h; lo = *(uint16_t*)&l;
}
__device__ __forceinline__ void pack8(const float* v, uint4& H, uint4& L) {
    uint16_t h[8], l[8];
#pragma unroll
    for (int i = 0; i < 8; i++) split1(v[i], h[i], l[i]);
    H.x = (uint32_t)h[0] | ((uint32_t)h[1] << 16);
    H.y = (uint32_t)h[2] | ((uint32_t)h[3] << 16);
    H.z = (uint32_t)h[4] | ((uint32_t)h[5] << 16);
    H.w = (uint32_t)h[6] | ((uint32_t)h[7] << 16);
    L.x = (uint32_t)l[0] | ((uint32_t)l[1] << 16);
    L.y = (uint32_t)l[2] | ((uint32_t)l[3] << 16);
    L.z = (uint32_t)l[4] | ((uint32_t)l[5] << 16);
    L.w = (uint32_t)l[6] | ((uint32_t)l[7] << 16);
}

// ---------------- zero stats ----------------
__global__ void zero_stats_kernel() {
    int t = threadIdx.x;
    if (t < 9) g_m[t] = 0.f;
    if (t < COUT) { g_s1[t] = 0.f; g_q1[t] = 0.f; g_s2[t] = 0.f; g_q2[t] = 0.f; }
}

// ---------------- bias concat + weight split (bf16 hi/lo, [K,N]) ----------
__global__ void bias_kv_kernel(const float* __restrict__ bk, const float* __restrict__ bv) {
    int i = blockIdx.x * 256 + threadIdx.x;
    if (i < 512) g_bkv[i] = (i < 256) ? bk[i] : bv[i - 256];
}

__global__ void split_w_kernel(const float* __restrict__ wq,
                               const float* __restrict__ wk, const float* __restrict__ wv,
                               const float* __restrict__ wp2, const float* __restrict__ ww) {
    int i = blockIdx.x * 256 + threadIdx.x;
    if (i >= TOTW) return;
    float val;
    if (i < OKV) {                       // wq [256,256]
        val = wq[i];
    } else if (i < OP2) {                // wkv [256,512]: row k = [wk_k | wv_k]
        int j = i - OKV, k = j >> 9, n = j & 511;
        val = (n < 256) ? wk[k*256 + n] : wv[k*256 + (n - 256)];
    } else if (i < OW) {                 // wp2 [64,256]
        val = wp2[i - OP2];
    } else {                             // ww [256,256]
        val = ww[i - OW];
    }
    uint16_t h, l;
    split1(val, h, l);
    g_bth[i] = h; g_btl[i] = l;
}

// ---------------- kNN: exact grid-accelerated ----------------
// d2 formula bit-identical to the passing version (all _rn intrinsics).
__device__ __forceinline__ float norm3_ref(float x, float y, float z) {
    return __fadd_rn(__fadd_rn(__fmul_rn(x, x), __fmul_rn(y, y)), __fmul_rn(z, z));
}
__device__ __forceinline__ int gcell(float v) {
    int c = (int)(v * (float)GDIM);
    return c < 0 ? 0 : (c > GDIM-1 ? GDIM-1 : c);
}

__global__ void grid_zero_kernel() {
    int t = threadIdx.x;
    if (t < GCELLS) g_cellCnt[t] = 0;
}
__global__ void grid_count_kernel(const float* __restrict__ xyz_i) {
    int i = blockIdx.x * 256 + threadIdx.x;
    if (i >= N_PTS) return;
    int cx = gcell(xyz_i[i*3+0]);
    int cy = gcell(xyz_i[i*3+1]);
    int cz = gcell(xyz_i[i*3+2]);
    atomicAdd(&g_cellCnt[(cz*GDIM + cy)*GDIM + cx], 1);
}
__global__ void grid_scan_kernel() {
    __shared__ int s[GCELLS];
    int t = threadIdx.x;                  // 512
    int own = g_cellCnt[t];
    s[t] = own;
    __syncthreads();
    for (int off = 1; off < GCELLS; off <<= 1) {
        int u = 0;
        if (t >= off) u = s[t - off];
        __syncthreads();
        s[t] += u;
        __syncthreads();
    }
    g_cellStart[t] = s[t] - own;          // exclusive
    if (t == GCELLS-1) g_cellStart[GCELLS] = N_PTS;
    g_cellFill[t] = 0;
}
__global__ void grid_scatter_kernel(const float* __restrict__ xyz_i) {
    int i = blockIdx.x * 256 + threadIdx.x;
    if (i >= N_PTS) return;
    float x = xyz_i[i*3+0], y = xyz_i[i*3+1], z = xyz_i[i*3+2];
    int cell = (gcell(z)*GDIM + gcell(y))*GDIM + gcell(x);
    int pos = g_cellStart[cell] + atomicAdd(&g_cellFill[cell], 1);
    g_spts[pos] = make_float4(x, y, z, norm3_ref(x, y, z));
    g_sidx[pos] = i;
}

// warp per query: enumerate cells within KRAD, exact d2, lexicographic top-16.
__global__ void knn_grid_kernel(const float* __restrict__ xyz_last) {
    __shared__ float ld[QPB][KNN][32];
    __shared__ int   li[QPB][KNN][32];
    const int tid = threadIdx.x;
    const int w = tid >> 5, lane = tid & 31;
    const int q = blockIdx.x * QPB + w;
    const float qx = xyz_last[q*3+0];
    const float qy = xyz_last[q*3+1];
    const float qz = xyz_last[q*3+2];
    const float nq = norm3_ref(qx, qy, qz);
    const float cw = 1.f / (float)GDIM;

    float dist[KNN];
    int   idx [KNN];
#pragma unroll
    for (int j = 0; j < KNN; j++) { dist[j] = FLT_MAX; idx[j] = 0x7fffffff; }

    int zlo = (int)floorf((qz - KRAD) * (float)GDIM); if (zlo < 0) zlo = 0;
    int zhi = (int)floorf((qz + KRAD) * (float)GDIM); if (zhi > GDIM-1) zhi = GDIM-1;
    int ylo = (int)floorf((qy - KRAD) * (float)GDIM); if (ylo < 0) ylo = 0;
    int yhi = (int)floorf((qy + KRAD) * (float)GDIM); if (yhi > GDIM-1) yhi = GDIM-1;

    for (int z = zlo; z <= zhi; z++) {
        float dz = fmaxf(0.f, fmaxf((float)z * cw - qz, qz - (float)(z+1) * cw));
        float dz2 = dz * dz;
        for (int y = ylo; y <= yhi; y++) {
            float dy = fmaxf(0.f, fmaxf((float)y * cw - qy, qy - (float)(y+1) * cw));
            float dyz2 = dz2 + dy * dy;
            if (dyz2 > KRAD2) continue;
            float xr = sqrtf(KRAD2 - dyz2) + 1e-6f;
            int xlo = (int)floorf((qx - xr) * (float)GDIM); if (xlo < 0) xlo = 0;
            int xhi = (int)floorf((qx + xr) * (float)GDIM); if (xhi > GDIM-1) xhi = GDIM-1;
            int base = (z*GDIM + y)*GDIM;
            int s = g_cellStart[base + xlo];
            int e = g_cellStart[base + xhi + 1];
            for (int i = s + lane; i < e; i += 32) {
                float4 pv = g_spts[i];
                float t = __fmul_rn(qx, pv.x);
                t = __fmaf_rn(qy, pv.y, t);
                t = __fmaf_rn(qz, pv.z, t);
                float d2 = __fsub_rn(__fadd_rn(nq, pv.w), __fmul_rn(2.0f, t));
                int gi = g_sidx[i];
                bool ins = (d2 < dist[KNN-1]) || (d2 == dist[KNN-1] && gi < idx[KNN-1]);
                if (ins) {
                    dist[KNN-1] = d2;
                    idx[KNN-1]  = gi;
#pragma unroll
                    for (int j = KNN-1; j > 0; j--) {
                        float da = dist[j-1], db = dist[j];
                        int   ia = idx[j-1],  ib = idx[j];
                        bool sw = (db < da) || (db == da && ib < ia);
                        dist[j-1] = sw ? db : da;
                        dist[j]   = sw ? da : db;
                        idx[j-1]  = sw ? ib : ia;
                        idx[j]    = sw ? ia : ib;
                    }
                }
            }
        }
    }
#pragma unroll
    for (int j = 0; j < KNN; j++) { ld[w][j][lane] = dist[j]; li[w][j][lane] = idx[j]; }
    __syncwarp();

    int pos = 0;
    float last_v = FLT_MAX;
    for (int r = 0; r < KNN; r++) {
        float v = (pos < KNN) ? ld[w][pos][lane] : FLT_MAX;
        int  gi = (pos < KNN) ? li[w][pos][lane] : 0x7fffffff;
        int  owner = lane;
#pragma unroll
        for (int off = 16; off > 0; off >>= 1) {
            float v2  = __shfl_xor_sync(0xffffffffu, v, off);
            int   g2  = __shfl_xor_sync(0xffffffffu, gi, off);
            int   o2  = __shfl_xor_sync(0xffffffffu, owner, off);
            if (v2 < v || (v2 == v && g2 < gi)) { v = v2; gi = g2; owner = o2; }
        }
        if (lane == 0) g_idx[q*KNN + r] = gi;
        last_v = v;
        if (lane == owner) pos++;
    }
    // soundness: every non-enumerated point has d2 > KRAD2 (minus fp slack)
    bool ok = (last_v + 1e-4f < KRAD2);
    if (lane == 0) g_fb[q] = ok ? 0 : 1;
}

// brute-force fallback for flagged queries (bit-identical math; block-gated)
__global__ void knn_fb_kernel(const float* __restrict__ xyz_i,
                              const float* __restrict__ xyz_last) {
    __shared__ float4 sp[TILE];
    __shared__ float ld[QPB][KNN][32];
    __shared__ int   li[QPB][KNN][32];
    __shared__ int   sflag;
    const int tid = threadIdx.x;
    const int w = tid >> 5, lane = tid & 31;
    const int q = blockIdx.x * QPB + w;
    if (tid == 0) sflag = 0;
    __syncthreads();
    const int myflag = g_fb[q];
    if (lane == 0 && myflag) atomicOr(&sflag, 1);
    __syncthreads();
    if (!sflag) return;

    const float qx = xyz_last[q*3+0];
    const float qy = xyz_last[q*3+1];
    const float qz = xyz_last[q*3+2];
    const float nq = norm3_ref(qx, qy, qz);

    float dist[KNN];
    int   idx [KNN];
#pragma unroll
    for (int j = 0; j < KNN; j++) { dist[j] = FLT_MAX; idx[j] = 0x7fffffff; }

    for (int t0 = 0; t0 < N_PTS; t0 += TILE) {
        __syncthreads();
        for (int p = tid; p < TILE; p += 256) {
            float x = xyz_i[(t0+p)*3+0];
            float y = xyz_i[(t0+p)*3+1];
            float z = xyz_i[(t0+p)*3+2];
            sp[p] = make_float4(x, y, z, norm3_ref(x, y, z));
        }
        __syncthreads();
        for (int i = lane; i < TILE; i += 32) {
            float4 pv = sp[i];
            float t = __fmul_rn(qx, pv.x);
            t = __fmaf_rn(qy, pv.y, t);
            t = __fmaf_rn(qz, pv.z, t);
            float d2 = __fsub_rn(__fadd_rn(nq, pv.w), __fmul_rn(2.0f, t));
            int gi = t0 + i;
            bool ins = (d2 < dist[KNN-1]) || (d2 == dist[KNN-1] && gi < idx[KNN-1]);
            if (ins) {
                dist[KNN-1] = d2;
                idx[KNN-1]  = gi;
#pragma unroll
                for (int j = KNN-1; j > 0; j--) {
                    float da = dist[j-1], db = dist[j];
                    int   ia = idx[j-1],  ib = idx[j];
                    bool sw = (db < da) || (db == da && ib < ia);
                    dist[j-1] = sw ? db : da;
                    dist[j]   = sw ? da : db;
                    idx[j-1]  = sw ? ib : ia;
                    idx[j]    = sw ? ia : ib;
                }
            }
        }
    }
#pragma unroll
    for (int j = 0; j < KNN; j++) { ld[w][j][lane] = dist[j]; li[w][j][lane] = idx[j]; }
    __syncwarp();

    int pos = 0;
    for (int r = 0; r < KNN; r++) {
        float v = (pos < KNN) ? ld[w][pos][lane] : FLT_MAX;
        int  gi = (pos < KNN) ? li[w][pos][lane] : 0x7fffffff;
        int  owner = lane;
#pragma unroll
        for (int off = 16; off > 0; off >>= 1) {
            float v2  = __shfl_xor_sync(0xffffffffu, v, off);
            int   g2  = __shfl_xor_sync(0xffffffffu, gi, off);
            int   o2  = __shfl_xor_sync(0xffffffffu, owner, off);
            if (v2 < v || (v2 == v && g2 < gi)) { v = v2; gi = g2; owner = o2; }
        }
        if (lane == 0 && myflag) g_idx[q*KNN + r] = gi;
        if (lane == owner) pos++;
    }
}

// ---------------- pe4 moments (analytic BN stats for pe layer) ----------------
__global__ void moments_kernel(const float* __restrict__ xyz_i,
                               const float* __restrict__ xyz_last) {
    float a0=0,a1=0,a2=0,a3=0,a4=0,a5=0,a6=0,a7=0,a8=0;
    for (int s = blockIdx.x * 256 + threadIdx.x; s < NK; s += gridDim.x * 256) {
        int n = s >> 4;
        int j = g_idx[s];
        float x = xyz_i[j*3+0] - xyz_last[n*3+0];
        float y = xyz_i[j*3+1] - xyz_last[n*3+1];
        float z = xyz_i[j*3+2] - xyz_last[n*3+2];
        a0 += x; a1 += y; a2 += z;
        a3 = fmaf(x,x,a3); a4 = fmaf(y,y,a4); a5 = fmaf(z,z,a5);
        a6 = fmaf(x,y,a6); a7 = fmaf(x,z,a7); a8 = fmaf(y,z,a8);
    }
    float v[9] = {a0,a1,a2,a3,a4,a5,a6,a7,a8};
#pragma unroll
    for (int i = 0; i < 9; i++) {
#pragma unroll
        for (int off = 16; off > 0; off >>= 1)
            v[i] += __shfl_xor_sync(0xffffffffu, v[i], off);
    }
    if ((threadIdx.x & 31) == 0) {
#pragma unroll
        for (int i = 0; i < 9; i++) atomicAdd(&g_m[i], v[i]);
    }
}

__global__ void finalize_pe_kernel(const float* __restrict__ gp, const float* __restrict__ bp_,
                                   const float* __restrict__ wp1, const float* __restrict__ bp1,
                                   const float* __restrict__ t_i, const float* __restrict__ t_last) {
    int c = threadIdx.x;                 // 64
    float inv = 1.f / (float)NK;
    float mx = g_m[0]*inv, my = g_m[1]*inv, mz = g_m[2]*inv;
    float exx = g_m[3]*inv, eyy = g_m[4]*inv, ezz = g_m[5]*inv;
    float exy = g_m[6]*inv, exz = g_m[7]*inv, eyz = g_m[8]*inv;
    float w0 = wp1[c], w1 = wp1[64+c], w2 = wp1[128+c], w3 = wp1[192+c];
    float a  = bp1[c] + w3*(t_i[0] - t_last[0]);
    float lm = w0*mx + w1*my + w2*mz;
    float mean = a + lm;
    float e2 = a*a + 2.f*a*lm
             + w0*w0*exx + w1*w1*eyy + w2*w2*ezz
             + 2.f*(w0*w1*exy + w0*w2*exz + w1*w2*eyz);
    float var = e2 - mean*mean;
    float s = gp[c] * rsqrtf(var + EPS);
    g_pscale[c] = s;
    g_pshift[c] = bp_[c] - mean*s;
}

// ---------------- BN finalize (w1 / w2) ----------------
__global__ void finalize_kernel(const float* __restrict__ gamma,
                                const float* __restrict__ beta,
                                float invM, int which) {
    int c = threadIdx.x;
    const float* gs = (which == 1) ? g_s1 : g_s2;
    const float* gq = (which == 1) ? g_q1 : g_q2;
    float* sc = (which == 1) ? g_sc1 : g_sc2;
    float* sh = (which == 1) ? g_sh1 : g_sh2;
    float m = gs[c] * invM;
    float v = gq[c] * invM - m*m;
    float s = gamma[c] * rsqrtf(v + EPS);
    sc[c] = s;
    sh[c] = beta[c] - m*s;
}

// ---------------- mma.sync GEMM, 512 threads, 16 warps, 3-product bf16 split ----
template<int MODE>
__global__ __launch_bounds__(512, 1)
void mma_gemm(const float* __restrict__ A,
              const uint16_t* __restrict__ Bth, const uint16_t* __restrict__ Btl,
              const float* __restrict__ bias, float* __restrict__ C,
              int M, int N, int K,
              const float* __restrict__ xyz_i, const float* __restrict__ xyz_last,
              const float* __restrict__ t_i, const float* __restrict__ t_last,
              const float* __restrict__ wp1, const float* __restrict__ bp1) {
    __shared__ __align__(16) uint16_t Ah[128*ASTR], Al[128*ASTR];
    __shared__ __align__(16) uint16_t Bh[32*BSTR], Bl[32*BSTR];
    __shared__ float spx[128], spy[128], spz[128];
    __shared__ float swp[256], sbp[64], sps[64], ssh[64];
    __shared__ float ssc[256], ssh2[256];
    __shared__ float sbias[128], sstatS[128], sstatQ[128];

    const int tid = threadIdx.x;
    const int lane = tid & 31, wid = tid >> 5;
    const int wm = wid >> 2, wn = wid & 3;          // 4x4 warp grid, 32x32 tiles
    const int m0 = blockIdx.y * 128, n0 = blockIdx.x * 128;

    float dtv = 0.f;
    if (MODE == 1) {
        if (tid < 128) {
            int m = m0 + tid;
            int n = m >> 4;
            int j = g_idx[m];
            spx[tid] = xyz_i[j*3+0] - xyz_last[n*3+0];
            spy[tid] = xyz_i[j*3+1] - xyz_last[n*3+1];
            spz[tid] = xyz_i[j*3+2] - xyz_last[n*3+2];
        }
        if (tid < 256) swp[tid] = wp1[tid];
        if (tid < 64) { sbp[tid] = bp1[tid]; sps[tid] = g_pscale[tid]; ssh[tid] = g_pshift[tid]; }
        dtv = t_i[0] - t_last[0];
    }
    if (MODE == 2 && tid < 256) { ssc[tid] = g_sc1[tid]; ssh2[tid] = g_sh1[tid]; }
    if (tid < 128) { sbias[tid] = bias[n0 + tid]; sstatS[tid] = 0.f; sstatQ[tid] = 0.f; }
    if (MODE == 1 || MODE == 2) __syncthreads();

    float acc[2][4][4];
#pragma unroll
    for (int i = 0; i < 2; i++)
#pragma unroll
        for (int j = 0; j < 4; j++)
#pragma unroll
            for (int e = 0; e < 4; e++) acc[i][j][e] = 0.f;

    const int arow = tid >> 2, ac = (tid & 3) * 8;     // A: 128 rows x 32 k
    const int brow = tid >> 4, bc = (tid & 15) * 8;    // B: 32 k-rows x 128 n

    float4 a0r, a1r;
    uint4 bhr, blr;
    if (!((MODE == 1))) {
        a0r = *(const float4*)(A + (size_t)(m0 + arow)*K + ac);
        a1r = *(const float4*)(A + (size_t)(m0 + arow)*K + ac + 4);
    }
    bhr = *(const uint4*)(Bth + (size_t)brow*N + n0 + bc);
    blr = *(const uint4*)(Btl + (size_t)brow*N + n0 + bc);

    const uint32_t AhB = su32(Ah), AlB = su32(Al), BhB = su32(Bh), BlB = su32(Bl);
    uint32_t a_off[2], b_off[2];
#pragma unroll
    for (int mt = 0; mt < 2; mt++)
        a_off[mt] = (uint32_t)(((wm*32 + mt*16 + (lane & 15))*ASTR + (lane >> 4)*8) * 2);
#pragma unroll
    for (int p = 0; p < 2; p++)
        b_off[p] = (uint32_t)(((lane & 15)*BSTR + wn*32 + p*16 + (lane >> 4)*8) * 2);

    const int nst = K >> 5;
    for (int kt = 0; kt < nst; kt++) {
        const int kb = kt * 32;
        if (MODE == 1) {
            float px = spx[arow], py = spy[arow], pz = spz[arow];
            float v[8];
#pragma unroll
            for (int e = 0; e < 8; e++) {
                int c = kb + ac + e;
                float hh = sbp[c];
                hh = fmaf(px,  swp[c],     hh);
                hh = fmaf(py,  swp[64+c],  hh);
                hh = fmaf(pz,  swp[128+c], hh);
                hh = fmaf(dtv, swp[192+c], hh);
                float x = fmaf(hh, sps[c], ssh[c]);
                v[e] = (x >= 0.f) ? x : SLOPE*x;
            }
            uint4 H, L;
            pack8(v, H, L);
            *(uint4*)&Ah[arow*ASTR + ac] = H;
            *(uint4*)&Al[arow*ASTR + ac] = L;
        } else {
            float v[8] = {a0r.x, a0r.y, a0r.z, a0r.w, a1r.x, a1r.y, a1r.z, a1r.w};
            if (MODE == 2) {
                int c = kb + ac;
#pragma unroll
                for (int e = 0; e < 8; e++) {
                    float x = fmaf(v[e], ssc[c+e], ssh2[c+e]);
                    v[e] = (x >= 0.f) ? x : SLOPE*x;
                }
            }
            uint4 H, L;
            pack8(v, H, L);
            *(uint4*)&Ah[arow*ASTR + ac] = H;
            *(uint4*)&Al[arow*ASTR + ac] = L;
        }
        *(uint4*)&Bh[brow*BSTR + bc] = bhr;
        *(uint4*)&Bl[brow*BSTR + bc] = blr;
        __syncthreads();

        if (kt + 1 < nst) {
            const int kn = kb + 32;
            if (MODE != 1) {
                a0r = *(const float4*)(A + (size_t)(m0 + arow)*K + kn + ac);
                a1r = *(const float4*)(A + (size_t)(m0 + arow)*K + kn + ac + 4);
            }
            bhr = *(const uint4*)(Bth + (size_t)(kn + brow)*N + n0 + bc);
            blr = *(const uint4*)(Btl + (size_t)(kn + brow)*N + n0 + bc);
        }

#pragma unroll
        for (int ko = 0; ko < 2; ko++) {
            uint32_t ah[2][4], al_[2][4];
#pragma unroll
            for (int mt = 0; mt < 2; mt++) {
                ldsm4(ah[mt],  AhB + a_off[mt] + ko*32);
                ldsm4(al_[mt], AlB + a_off[mt] + ko*32);
            }
            uint32_t bh[4][2], bl[4][2];
#pragma unroll
            for (int p = 0; p < 2; p++) {
                uint32_t r[4];
                ldsm4t(r, BhB + b_off[p] + ko*16*BSTR*2);
                bh[2*p][0] = r[0]; bh[2*p][1] = r[1];
                bh[2*p+1][0] = r[2]; bh[2*p+1][1] = r[3];
                ldsm4t(r, BlB + b_off[p] + ko*16*BSTR*2);
                bl[2*p][0] = r[0]; bl[2*p][1] = r[1];
                bl[2*p+1][0] = r[2]; bl[2*p+1][1] = r[3];
            }
#pragma unroll
            for (int mt = 0; mt < 2; mt++)
#pragma unroll
                for (int nt = 0; nt < 4; nt++) {
                    mma16816(acc[mt][nt], ah[mt],  bh[nt]);
                    mma16816(acc[mt][nt], ah[mt],  bl[nt]);
                    mma16816(acc[mt][nt], al_[mt], bh[nt]);
                }
        }
        __syncthreads();
    }

    // ---- epilogue ----
    float colS[8], colQ[8];
#pragma unroll
    for (int i = 0; i < 8; i++) { colS[i] = 0.f; colQ[i] = 0.f; }

#pragma unroll
    for (int mt = 0; mt < 2; mt++) {
        int r0 = m0 + wm*32 + mt*16 + (lane >> 2);
        int r1 = r0 + 8;
        int j0 = 0, j1 = 0, p0 = 0, p1 = 0;
        if (MODE == 1) {
            j0 = g_idx[r0]; j1 = g_idx[r1];
            p0 = r0 >> 4;   p1 = r1 >> 4;
        }
#pragma unroll
        for (int nt = 0; nt < 4; nt++) {
            int cl = wn*32 + nt*8 + (lane & 3)*2;      // local col in [0,128)
            int c = n0 + cl;
            float v00 = acc[mt][nt][0] + sbias[cl],   v01 = acc[mt][nt][1] + sbias[cl+1];
            float v10 = acc[mt][nt][2] + sbias[cl],   v11 = acc[mt][nt][3] + sbias[cl+1];
            if (MODE == 1) {
                float2 q0 = *(const float2*)(g_q  + (size_t)p0*256 + c);
                float2 q1 = *(const float2*)(g_q  + (size_t)p1*256 + c);
                float2 k0 = *(const float2*)(g_kv + (size_t)j0*512 + c);
                float2 k1 = *(const float2*)(g_kv + (size_t)j1*512 + c);
                v00 = q0.x - k0.x + v00; v01 = q0.y - k0.y + v01;
                v10 = q1.x - k1.x + v10; v11 = q1.y - k1.y + v11;
            }
            *(float2*)(C + (size_t)r0*N + c) = make_float2(v00, v01);
            *(float2*)(C + (size_t)r1*N + c) = make_float2(v10, v11);
            if (MODE != 0) {
                colS[nt*2+0] += v00 + v10;  colS[nt*2+1] += v01 + v11;
                colQ[nt*2+0] += v00*v00 + v10*v10;
                colQ[nt*2+1] += v01*v01 + v11*v11;
            }
        }
    }
    if (MODE != 0) {
#pragma unroll
        for (int i = 0; i < 8; i++) {
#pragma unroll
            for (int off = 4; off <= 16; off <<= 1) {
                colS[i] += __shfl_xor_sync(0xffffffffu, colS[i], off);
                colQ[i] += __shfl_xor_sync(0xffffffffu, colQ[i], off);
            }
        }
        if (lane < 4) {
#pragma unroll
            for (int nt = 0; nt < 4; nt++) {
#pragma unroll
                for (int j = 0; j < 2; j++) {
                    int cl = wn*32 + nt*8 + lane*2 + j;
                    atomicAdd(&sstatS[cl], colS[nt*2+j]);
                    atomicAdd(&sstatQ[cl], colQ[nt*2+j]);
                }
            }
        }
        __syncthreads();
        if (tid < 128) {
            float* gS = (MODE == 1) ? g_s1 : g_s2;
            float* gQ = (MODE == 1) ? g_q1 : g_q2;
            atomicAdd(&gS[n0 + tid], sstatS[tid]);
            atomicAdd(&gQ[n0 + tid], sstatQ[tid]);
        }
    }
}

// ---------------- final: bn2 + lrelu + softmax(K) + weighted v-sum ----------------
__global__ void final_kernel(float* __restrict__ out) {
    int n = blockIdx.x, c = threadIdx.x;
    __shared__ int sidx[KNN];
    if (c < KNN) sidx[c] = g_idx[n*KNN + c];
    __syncthreads();
    float sc = g_sc2[c], sh = g_sh2[c];
    float qv = g_q[(size_t)n*COUT + c];
    float z[KNN], w1v[KNN];
    float m = -FLT_MAX;
#pragma unroll
    for (int k = 0; k < KNN; k++) {
        float x = g_w2[((size_t)n*KNN + k)*COUT + c];
        w1v[k] = g_w1[((size_t)n*KNN + k)*COUT + c];
        x = x*sc + sh;
        x = (x >= 0.f) ? x : SLOPE*x;
        z[k] = x;
        m = fmaxf(m, x);
    }
    float den = 0.f, num = 0.f;
#pragma unroll
    for (int k = 0; k < KNN; k++) {
        float e = __expf(z[k] - m);
        const float* kvrow = g_kv + (size_t)sidx[k]*512;
        float v = kvrow[256 + c] + (w1v[k] - qv + kvrow[c]);
        den += e;
        num = fmaf(e, v, num);
    }
    out[(size_t)n*COUT + c] = num / den;
}

// ---------------- launch ----------------
extern "C" void kernel_launch(void* const* d_in, const int* in_sizes, int n_in,
                              void* d_out, int out_size) {
    const float* fea_i    = (const float*)d_in[0];
    const float* fea_last = (const float*)d_in[1];
    const float* xyz_i    = (const float*)d_in[2];
    const float* xyz_last = (const float*)d_in[3];
    const float* t_i      = (const float*)d_in[4];
    const float* t_last   = (const float*)d_in[5];
    const float* wp1 = (const float*)d_in[6];
    const float* bp1 = (const float*)d_in[7];
    const float* gp  = (const float*)d_in[8];
    const float* bp  = (const float*)d_in[9];
    const float* wp2 = (const float*)d_in[10];
    const float* bp2 = (const float*)d_in[11];
    const float* wq  = (const float*)d_in[12];
    const float* bq  = (const float*)d_in[13];
    const float* wk  = (const float*)d_in[14];
    const float* bk  = (const float*)d_in[15];
    const float* wv  = (const float*)d_in[16];
    const float* bv  = (const float*)d_in[17];
    const float* gw1 = (const float*)d_in[18];
    const float* bw1 = (const float*)d_in[19];
    const float* ww  = (const float*)d_in[20];
    const float* bw  = (const float*)d_in[21];
    const float* gw2 = (const float*)d_in[22];
    const float* bw2 = (const float*)d_in[23];
    float* out = (float*)d_out;

    void* p;
    cudaGetSymbolAddress(&p, g_q);   float* p_q   = (float*)p;
    cudaGetSymbolAddress(&p, g_kv);  float* p_kv  = (float*)p;
    cudaGetSymbolAddress(&p, g_bkv); float* p_bkv = (float*)p;
    cudaGetSymbolAddress(&p, g_bth); uint16_t* p_bth = (uint16_t*)p;
    cudaGetSymbolAddress(&p, g_btl); uint16_t* p_btl = (uint16_t*)p;
    cudaGetSymbolAddress(&p, g_w1);  float* p_w1  = (float*)p;
    cudaGetSymbolAddress(&p, g_w2);  float* p_w2  = (float*)p;

    zero_stats_kernel<<<1, 256>>>();
    bias_kv_kernel<<<2, 256>>>(bk, bv);
    split_w_kernel<<<(TOTW + 255)/256, 256>>>(wq, wk, wv, wp2, ww);

    // 1) kNN: grid build -> grid query -> fallback for flagged queries
    grid_zero_kernel<<<1, 512>>>();
    grid_count_kernel<<<N_PTS/256, 256>>>(xyz_i);
    grid_scan_kernel<<<1, 512>>>();
    grid_scatter_kernel<<<N_PTS/256, 256>>>(xyz_i);
    knn_grid_kernel<<<N_PTS/QPB, 256>>>(xyz_last);
    knn_fb_kernel<<<N_PTS/QPB, 256>>>(xyz_i, xyz_last);

    // 2) projections
    mma_gemm<0><<<dim3(2, 64), 512>>>(fea_last, p_bth + OQ,  p_btl + OQ,  bq,    p_q,  N_PTS, 256, CIN,
                                      nullptr, nullptr, nullptr, nullptr, nullptr, nullptr);
    mma_gemm<0><<<dim3(4, 64), 512>>>(fea_i,    p_bth + OKV, p_btl + OKV, p_bkv, p_kv, N_PTS, 512, CIN,
                                      nullptr, nullptr, nullptr, nullptr, nullptr, nullptr);

    // 3) analytic pe-BN stats
    moments_kernel<<<64, 256>>>(xyz_i, xyz_last);
    finalize_pe_kernel<<<1, HDIM>>>(gp, bp, wp1, bp1, t_i, t_last);

    // 4) pe GEMM (A generated) -> w1 = q - kf + pe directly, + BN1 stats
    mma_gemm<1><<<dim3(2, 1024), 512>>>(nullptr, p_bth + OP2, p_btl + OP2, bp2, p_w1, NK, 256, HDIM,
                                        xyz_i, xyz_last, t_i, t_last, wp1, bp1);
    finalize_kernel<<<1, COUT>>>(gw1, bw1, 1.f/(float)NK, 1);

    // 5) w2 GEMM + BN2 stats
    mma_gemm<2><<<dim3(2, 1024), 512>>>(p_w1, p_bth + OW, p_btl + OW, bw, p_w2, NK, 256, CIN,
                                        nullptr, nullptr, nullptr, nullptr, nullptr, nullptr);
    finalize_kernel<<<1, COUT>>>(gw2, bw2, 1.f/(float)NK, 2);

    // 6) softmax over K + weighted v-sum (pe reconstructed from w1)
    final_kernel<<<N_PTS, COUT>>>(out);
}